// round 11
// baseline (speedup 1.0000x reference)
#include <cuda_runtime.h>
#include <cuda_bf16.h>
#include <math.h>

#define N_TOK 6144
#define D_MODEL 256
#define N_HEADS 4
#define D_HEAD 64
#define D_FF 1024
#define LN_EPS 1e-5f

// ---------------- scratch (static device globals; no allocation) ----------------
__device__ float g_qkv [N_TOK * 3 * D_MODEL];           // fp32 (attention reads)
__device__ float g_x1  [N_TOK * D_MODEL];
__device__ __nv_bfloat16 g_xb   [N_TOK * D_MODEL];      // bf16 activations/weights
__device__ __nv_bfloat16 g_attnb[N_TOK * D_MODEL];
__device__ __nv_bfloat16 g_x1b  [N_TOK * D_MODEL];
__device__ __nv_bfloat16 g_ffhb [N_TOK * D_FF];
__device__ __nv_bfloat16 g_wq   [D_MODEL * 3 * D_MODEL];
__device__ __nv_bfloat16 g_wo   [D_MODEL * D_MODEL];
__device__ __nv_bfloat16 g_w1   [D_MODEL * D_FF];
__device__ __nv_bfloat16 g_w2   [D_FF * D_MODEL];

// ---------------- helpers --------------------------------------------------------
__device__ __forceinline__ void cp16(void* smem_dst, const void* gsrc) {
    unsigned d = (unsigned)__cvta_generic_to_shared(smem_dst);
    asm volatile("cp.async.cg.shared.global [%0], [%1], 16;\n" :: "r"(d), "l"(gsrc));
}
__device__ __forceinline__ void cp_commit() { asm volatile("cp.async.commit_group;\n"); }
template<int NLEFT>
__device__ __forceinline__ void cp_wait()   { asm volatile("cp.async.wait_group %0;\n" :: "n"(NLEFT)); }

__device__ __forceinline__ void ldsm_x4(unsigned& r0, unsigned& r1, unsigned& r2, unsigned& r3,
                                        const void* p) {
    unsigned a = (unsigned)__cvta_generic_to_shared(p);
    asm volatile("ldmatrix.sync.aligned.m8n8.x4.shared.b16 {%0,%1,%2,%3}, [%4];"
                 : "=r"(r0), "=r"(r1), "=r"(r2), "=r"(r3) : "r"(a));
}
__device__ __forceinline__ void ldsm_x2t(unsigned& r0, unsigned& r1, const void* p) {
    unsigned a = (unsigned)__cvta_generic_to_shared(p);
    asm volatile("ldmatrix.sync.aligned.m8n8.x2.trans.shared.b16 {%0,%1}, [%2];"
                 : "=r"(r0), "=r"(r1) : "r"(a));
}
__device__ __forceinline__ void mma_bf16(
    float& c0, float& c1, float& c2, float& c3,
    unsigned a0, unsigned a1, unsigned a2, unsigned a3,
    unsigned b0, unsigned b1)
{
    asm volatile(
        "mma.sync.aligned.m16n8k16.row.col.f32.bf16.bf16.f32 "
        "{%0,%1,%2,%3}, {%4,%5,%6,%7}, {%8,%9}, {%0,%1,%2,%3};\n"
        : "+f"(c0), "+f"(c1), "+f"(c2), "+f"(c3)
        : "r"(a0), "r"(a1), "r"(a2), "r"(a3), "r"(b0), "r"(b1));
}

#define BK 64
#define A_STR 72    // 64 + 8 pad words; 144B row stride -> conflict-free ldmatrix

// ---------------- big bf16 GEMM (QKV / FF1): 128x128, BK=64, 3-stage ------------
#define NSTG 3
struct BigCfg {
    static constexpr int B_STR = 136;
    static constexpr int SMEM  = (NSTG * 128 * A_STR + NSTG * BK * B_STR) * 2;  // 107520
};

template<int K, int N, bool DOGELU, bool OUTBF16>
__global__ __launch_bounds__(256, 2) void gemm_bf16_k(
    const __nv_bfloat16* __restrict__ A, const __nv_bfloat16* __restrict__ B,
    const float* __restrict__ bias, void* __restrict__ Cv)
{
    constexpr int B_STR = BigCfg::B_STR;
    constexpr int WM = 64, WN = 32, MI = 4, NI = 4, KS = BK / 16;

    extern __shared__ __nv_bfloat16 smdyn[];
    typedef __nv_bfloat16 (*AsT)[128][A_STR];
    typedef __nv_bfloat16 (*BsT)[BK][B_STR];
    AsT As = reinterpret_cast<AsT>(smdyn);
    BsT Bs = reinterpret_cast<BsT>(smdyn + NSTG * 128 * A_STR);

    const int tid  = threadIdx.x;
    const int row0 = blockIdx.y * 128;
    const int col0 = blockIdx.x * 128;
    const int w    = tid >> 5;
    const int lane = tid & 31;
    const int wm = w & 1;
    const int wn = w >> 1;
    const int g  = lane >> 2;
    const int t4 = lane & 3;

    float acc[MI][NI][4];
#pragma unroll
    for (int mi = 0; mi < MI; mi++)
#pragma unroll
        for (int ni = 0; ni < NI; ni++)
#pragma unroll
            for (int r = 0; r < 4; r++) acc[mi][ni][r] = 0.f;

    auto stage = [&](int kt, int buf) {
#pragma unroll
        for (int c = tid; c < 128 * 8; c += 256) {
            int r = c >> 3, col = (c & 7) * 8;
            cp16(&As[buf][r][col], A + (size_t)(row0 + r) * K + kt + col);
        }
#pragma unroll
        for (int c = tid; c < 8 * 128; c += 256) {
            int r = c >> 4, col = (c & 15) * 8;
            cp16(&Bs[buf][r][col], B + (size_t)(kt + r) * N + col0 + col);
        }
        cp_commit();
    };

    constexpr int T = K / BK;
    stage(0, 0);
    stage(BK, 1);

    const int a_row = lane & 15;
    const int a_col = ((lane >> 4) << 3);
    const int b_row = lane & 15;

    for (int t = 0; t < T; t++) {
        cp_wait<1>();
        __syncthreads();
        if (t + 2 < T) stage((t + 2) * BK, (t + 2) % 3);
        else cp_commit();
        const int buf = t % 3;

#pragma unroll
        for (int ks = 0; ks < KS; ks++) {
            const int kc = ks * 16;
            unsigned af[MI][4], bf[NI][2];
#pragma unroll
            for (int mi = 0; mi < MI; mi++)
                ldsm_x4(af[mi][0], af[mi][1], af[mi][2], af[mi][3],
                        &As[buf][wm * WM + mi * 16 + a_row][kc + a_col]);
#pragma unroll
            for (int ni = 0; ni < NI; ni++)
                ldsm_x2t(bf[ni][0], bf[ni][1], &Bs[buf][kc + b_row][wn * WN + ni * 8]);
#pragma unroll
            for (int mi = 0; mi < MI; mi++)
#pragma unroll
                for (int ni = 0; ni < NI; ni++)
                    mma_bf16(acc[mi][ni][0], acc[mi][ni][1], acc[mi][ni][2], acc[mi][ni][3],
                             af[mi][0], af[mi][1], af[mi][2], af[mi][3],
                             bf[ni][0], bf[ni][1]);
        }
    }

#pragma unroll
    for (int mi = 0; mi < MI; mi++) {
        const int r0g = row0 + wm * WM + mi * 16 + g;
#pragma unroll
        for (int ni = 0; ni < NI; ni++) {
            const int c = col0 + wn * WN + ni * 8 + t4 * 2;
            const float bx = bias[c], by = bias[c + 1];
            float v0 = acc[mi][ni][0] + bx, v1 = acc[mi][ni][1] + by;
            float v2 = acc[mi][ni][2] + bx, v3 = acc[mi][ni][3] + by;
            if (DOGELU) {
                v0 = 0.5f * v0 * (1.f + erff(v0 * 0.70710678118654752f));
                v1 = 0.5f * v1 * (1.f + erff(v1 * 0.70710678118654752f));
                v2 = 0.5f * v2 * (1.f + erff(v2 * 0.70710678118654752f));
                v3 = 0.5f * v3 * (1.f + erff(v3 * 0.70710678118654752f));
            }
            if (OUTBF16) {
                __nv_bfloat16* C = (__nv_bfloat16*)Cv;
                *reinterpret_cast<__nv_bfloat162*>(C + (size_t)r0g * N + c) =
                    __floats2bfloat162_rn(v0, v1);
                *reinterpret_cast<__nv_bfloat162*>(C + (size_t)(r0g + 8) * N + c) =
                    __floats2bfloat162_rn(v2, v3);
            } else {
                float* C = (float*)Cv;
                *reinterpret_cast<float2*>(C + (size_t)r0g * N + c)       = make_float2(v0, v1);
                *reinterpret_cast<float2*>(C + (size_t)(r0g + 8) * N + c) = make_float2(v2, v3);
            }
        }
    }
}

// ---------------- fused GEMM + bias + residual + LayerNorm ----------------------
// C-rows fully owned by CTA: BM=32 x BN=256(=D_MODEL), BK=64, 2-stage.
// 8 warps, each a 32x32 warp tile (wn = warp id). Epilogue: z = acc+bias+res,
// row-reduce (shuffle over t4 + smem atomics), normalize, write fp32 (+bf16).
struct FuseCfg {
    static constexpr int B_STR = 264;
    static constexpr int SMEM  = (2 * 32 * A_STR + 2 * BK * B_STR) * 2 + 64 * 4;  // 77056
};

template<int K, bool OUTB>
__global__ __launch_bounds__(256, 2) void gemm_ln_fused(
    const __nv_bfloat16* __restrict__ A, const __nv_bfloat16* __restrict__ B,
    const float* __restrict__ bias, const float* __restrict__ res,
    const float* __restrict__ lng, const float* __restrict__ lnb,
    float* __restrict__ outf, __nv_bfloat16* __restrict__ outb)
{
    constexpr int B_STR = FuseCfg::B_STR;
    constexpr int MI = 2, NI = 4, KS = BK / 16;

    extern __shared__ __nv_bfloat16 smdyn[];
    typedef __nv_bfloat16 (*AsT)[32][A_STR];
    typedef __nv_bfloat16 (*BsT)[BK][B_STR];
    AsT As = reinterpret_cast<AsT>(smdyn);
    BsT Bs = reinterpret_cast<BsT>(smdyn + 2 * 32 * A_STR);
    float* rsum   = reinterpret_cast<float*>(smdyn + 2 * 32 * A_STR + 2 * BK * B_STR);
    float* rsumsq = rsum + 32;

    const int tid  = threadIdx.x;
    const int row0 = blockIdx.x * 32;
    const int wn   = tid >> 5;           // warp -> 32-col slice
    const int lane = tid & 31;
    const int g  = lane >> 2;
    const int t4 = lane & 3;

    if (tid < 32) { rsum[tid] = 0.f; rsumsq[tid] = 0.f; }

    float acc[MI][NI][4];
#pragma unroll
    for (int mi = 0; mi < MI; mi++)
#pragma unroll
        for (int ni = 0; ni < NI; ni++)
#pragma unroll
            for (int r = 0; r < 4; r++) acc[mi][ni][r] = 0.f;

    auto stage = [&](int kt, int buf) {
        {   // A: 32 x 64 -> 256 chunks, 1 per thread
            int r = tid >> 3, col = (tid & 7) * 8;
            cp16(&As[buf][r][col], A + (size_t)(row0 + r) * K + kt + col);
        }
#pragma unroll
        for (int c = tid; c < 8 * 256; c += 256) {   // B: 64 x 256 -> 2048 chunks
            int r = c >> 5, col = (c & 31) * 8;
            cp16(&Bs[buf][r][col], B + (size_t)(kt + r) * D_MODEL + col);
        }
        cp_commit();
    };

    constexpr int T = K / BK;
    stage(0, 0);

    const int a_row = lane & 15;
    const int a_col = ((lane >> 4) << 3);
    const int b_row = lane & 15;

    auto load_frags = [&](unsigned (&af)[MI][4], unsigned (&bf)[NI][2], int buf, int ks) {
        const int kc = ks * 16;
#pragma unroll
        for (int mi = 0; mi < MI; mi++)
            ldsm_x4(af[mi][0], af[mi][1], af[mi][2], af[mi][3],
                    &As[buf][mi * 16 + a_row][kc + a_col]);
#pragma unroll
        for (int ni = 0; ni < NI; ni++)
            ldsm_x2t(bf[ni][0], bf[ni][1], &Bs[buf][kc + b_row][wn * 32 + ni * 8]);
    };

    for (int t = 0; t < T; t++) {
        cp_wait<0>();
        __syncthreads();
        if (t + 1 < T) stage((t + 1) * BK, (t + 1) & 1);
        const int buf = t & 1;

        unsigned af[2][MI][4], bf[2][NI][2];
        load_frags(af[0], bf[0], buf, 0);
#pragma unroll
        for (int ks = 0; ks < KS; ks++) {
            const int cur = ks & 1;
            if (ks + 1 < KS) load_frags(af[cur ^ 1], bf[cur ^ 1], buf, ks + 1);
#pragma unroll
            for (int mi = 0; mi < MI; mi++)
#pragma unroll
                for (int ni = 0; ni < NI; ni++)
                    mma_bf16(acc[mi][ni][0], acc[mi][ni][1], acc[mi][ni][2], acc[mi][ni][3],
                             af[cur][mi][0], af[cur][mi][1], af[cur][mi][2], af[cur][mi][3],
                             bf[cur][ni][0], bf[cur][ni][1]);
        }
    }

    // ---- epilogue: z = acc + bias + res; row-wise LN over 256 cols -------------
    // thread's rows: mi*16+g (r=0,1) and mi*16+g+8 (r=2,3); cols: wn*32+ni*8+t4*2+{0,1}
#pragma unroll
    for (int mi = 0; mi < MI; mi++) {
        const int ra = mi * 16 + g, rb = ra + 8;
#pragma unroll
        for (int ni = 0; ni < NI; ni++) {
            const int c = wn * 32 + ni * 8 + t4 * 2;
            const float2 bv = *reinterpret_cast<const float2*>(bias + c);
            const float2 res_a = *reinterpret_cast<const float2*>(res + (size_t)(row0 + ra) * D_MODEL + c);
            const float2 res_b = *reinterpret_cast<const float2*>(res + (size_t)(row0 + rb) * D_MODEL + c);
            acc[mi][ni][0] += bv.x + res_a.x;
            acc[mi][ni][1] += bv.y + res_a.y;
            acc[mi][ni][2] += bv.x + res_b.x;
            acc[mi][ni][3] += bv.y + res_b.y;
        }
    }
    // partial sums per row over this thread's 8 cols
#pragma unroll
    for (int mi = 0; mi < MI; mi++) {
        float sa = 0.f, qa = 0.f, sb = 0.f, qb = 0.f;
#pragma unroll
        for (int ni = 0; ni < NI; ni++) {
            sa += acc[mi][ni][0] + acc[mi][ni][1];
            qa += acc[mi][ni][0] * acc[mi][ni][0] + acc[mi][ni][1] * acc[mi][ni][1];
            sb += acc[mi][ni][2] + acc[mi][ni][3];
            qb += acc[mi][ni][2] * acc[mi][ni][2] + acc[mi][ni][3] * acc[mi][ni][3];
        }
        // reduce over the 4 lanes (t4) sharing each row
#pragma unroll
        for (int m = 1; m <= 2; m <<= 1) {
            sa += __shfl_xor_sync(0xffffffffu, sa, m);
            qa += __shfl_xor_sync(0xffffffffu, qa, m);
            sb += __shfl_xor_sync(0xffffffffu, sb, m);
            qb += __shfl_xor_sync(0xffffffffu, qb, m);
        }
        if (t4 == 0) {
            atomicAdd(&rsum[mi * 16 + g], sa);
            atomicAdd(&rsumsq[mi * 16 + g], qa);
            atomicAdd(&rsum[mi * 16 + g + 8], sb);
            atomicAdd(&rsumsq[mi * 16 + g + 8], qb);
        }
    }
    __syncthreads();

#pragma unroll
    for (int mi = 0; mi < MI; mi++) {
        const int ra = mi * 16 + g, rb = ra + 8;
        const float mua = rsum[ra] * (1.f / D_MODEL);
        const float iva = rsqrtf(rsumsq[ra] * (1.f / D_MODEL) - mua * mua + LN_EPS);
        const float mub = rsum[rb] * (1.f / D_MODEL);
        const float ivb = rsqrtf(rsumsq[rb] * (1.f / D_MODEL) - mub * mub + LN_EPS);
#pragma unroll
        for (int ni = 0; ni < NI; ni++) {
            const int c = wn * 32 + ni * 8 + t4 * 2;
            const float2 gv = *reinterpret_cast<const float2*>(lng + c);
            const float2 bv = *reinterpret_cast<const float2*>(lnb + c);
            float o0 = (acc[mi][ni][0] - mua) * iva * gv.x + bv.x;
            float o1 = (acc[mi][ni][1] - mua) * iva * gv.y + bv.y;
            float o2 = (acc[mi][ni][2] - mub) * ivb * gv.x + bv.x;
            float o3 = (acc[mi][ni][3] - mub) * ivb * gv.y + bv.y;
            *reinterpret_cast<float2*>(outf + (size_t)(row0 + ra) * D_MODEL + c) = make_float2(o0, o1);
            *reinterpret_cast<float2*>(outf + (size_t)(row0 + rb) * D_MODEL + c) = make_float2(o2, o3);
            if (OUTB) {
                *reinterpret_cast<__nv_bfloat162*>(outb + (size_t)(row0 + ra) * D_MODEL + c) =
                    __floats2bfloat162_rn(o0, o1);
                *reinterpret_cast<__nv_bfloat162*>(outb + (size_t)(row0 + rb) * D_MODEL + c) =
                    __floats2bfloat162_rn(o2, o3);
            }
        }
    }
}

// ---------------- fp32 -> bf16 conversion of x + weights (one kernel) ------------
#define Q_X   393216           // 6144*256/4
#define Q_WQ  (Q_X  + 49152)   // 256*768/4
#define Q_WO  (Q_WQ + 16384)   // 256*256/4
#define Q_W1  (Q_WO + 65536)   // 256*1024/4
#define Q_W2  (Q_W1 + 65536)   // 1024*256/4  -> total 589824 quads
__global__ __launch_bounds__(256) void cvt_kernel(
    const float* __restrict__ x,  const float* __restrict__ wq,
    const float* __restrict__ wo, const float* __restrict__ w1,
    const float* __restrict__ w2,
    __nv_bfloat16* __restrict__ xb, __nv_bfloat16* __restrict__ wqb,
    __nv_bfloat16* __restrict__ wob, __nv_bfloat16* __restrict__ w1b,
    __nv_bfloat16* __restrict__ w2b)
{
    int q = blockIdx.x * 256 + threadIdx.x;
    const float* s; __nv_bfloat16* d; int base;
    if      (q < Q_X)  { s = x;  d = xb;  base = 0;    }
    else if (q < Q_WQ) { s = wq; d = wqb; base = Q_X;  }
    else if (q < Q_WO) { s = wo; d = wob; base = Q_WQ; }
    else if (q < Q_W1) { s = w1; d = w1b; base = Q_WO; }
    else               { s = w2; d = w2b; base = Q_W1; }
    size_t i = (size_t)(q - base) * 4;
    float4 v = *reinterpret_cast<const float4*>(s + i);
    reinterpret_cast<__nv_bfloat162*>(d + i)[0] = __floats2bfloat162_rn(v.x, v.y);
    reinterpret_cast<__nv_bfloat162*>(d + i)[1] = __floats2bfloat162_rn(v.z, v.w);
}

// ---------------- segment attention: one warp per (token, head), bf16 out -------
__global__ __launch_bounds__(256) void attn_kernel(
    const float* __restrict__ qkv, const int* __restrict__ doc,
    __nv_bfloat16* __restrict__ out)
{
    int wg = (blockIdx.x * 256 + threadIdx.x) >> 5;
    int lane = threadIdx.x & 31;
    if (wg >= N_TOK * N_HEADS) return;
    int i = wg >> 2;
    int h = wg & 3;

    const int my = doc[i];
    const int base = i - 16;
    const int idx = base + lane;
    int dv = -1;
    if (idx >= 0 && idx < N_TOK) dv = doc[idx];
    unsigned eq = __ballot_sync(0xffffffffu, dv == my);

    unsigned below = ~eq & 0xffffu;
    int s = (below == 0) ? base : base + (32 - __clz(below));
    unsigned above = ~eq & 0xfffe0000u;
    int e = (above == 0) ? base + 32 : base + (__ffs(above) - 1);
    if (below == 0) { while (s > 0 && doc[s - 1] == my) s--; }
    if (above == 0) { while (e < N_TOK && doc[e] == my) e++; }

    const float* q = qkv + (size_t)i * (3 * D_MODEL) + h * D_HEAD;
    float q0 = q[lane], q1 = q[lane + 32];
    const float* kbase = qkv + D_MODEL + h * D_HEAD;
    const float* vbase = qkv + 2 * D_MODEL + h * D_HEAD;

    float m = -3.4e38f, sum = 0.f, o0 = 0.f, o1 = 0.f;
    for (int j = s; j < e; j++) {
        const float* kr = kbase + (size_t)j * (3 * D_MODEL);
        float d = q0 * kr[lane] + q1 * kr[lane + 32];
#pragma unroll
        for (int off = 16; off; off >>= 1) d += __shfl_xor_sync(0xffffffffu, d, off);
        float sc = d * 0.125f;
        float mn = fmaxf(m, sc);
        float corr = __expf(m - mn);
        float p = __expf(sc - mn);
        const float* vr = vbase + (size_t)j * (3 * D_MODEL);
        sum = sum * corr + p;
        o0 = o0 * corr + p * vr[lane];
        o1 = o1 * corr + p * vr[lane + 32];
        m = mn;
    }
    float inv = 1.f / sum;
    out[(size_t)i * D_MODEL + h * D_HEAD + lane]      = __float2bfloat16(o0 * inv);
    out[(size_t)i * D_MODEL + h * D_HEAD + lane + 32] = __float2bfloat16(o1 * inv);
}

// ---------------- launch ---------------------------------------------------------
extern "C" void kernel_launch(void* const* d_in, const int* in_sizes, int n_in,
                              void* d_out, int out_size)
{
    const float* x      = (const float*)d_in[0];
    const int*   doc    = (const int*)  d_in[1];
    const float* qkv_w  = (const float*)d_in[2];
    const float* qkv_b  = (const float*)d_in[3];
    const float* out_w  = (const float*)d_in[4];
    const float* out_b  = (const float*)d_in[5];
    const float* ff_w1  = (const float*)d_in[6];
    const float* ff_b1  = (const float*)d_in[7];
    const float* ff_w2  = (const float*)d_in[8];
    const float* ff_b2  = (const float*)d_in[9];
    const float* ln1_g  = (const float*)d_in[10];
    const float* ln1_b  = (const float*)d_in[11];
    const float* ln2_g  = (const float*)d_in[12];
    const float* ln2_b  = (const float*)d_in[13];
    float* out = (float*)d_out;

    float *qkv, *x1;
    __nv_bfloat16 *xb, *attnb, *x1b, *ffhb, *wq, *wo, *w1, *w2;
    cudaGetSymbolAddress((void**)&qkv,   g_qkv);
    cudaGetSymbolAddress((void**)&x1,    g_x1);
    cudaGetSymbolAddress((void**)&xb,    g_xb);
    cudaGetSymbolAddress((void**)&attnb, g_attnb);
    cudaGetSymbolAddress((void**)&x1b,   g_x1b);
    cudaGetSymbolAddress((void**)&ffhb,  g_ffhb);
    cudaGetSymbolAddress((void**)&wq,    g_wq);
    cudaGetSymbolAddress((void**)&wo,    g_wo);
    cudaGetSymbolAddress((void**)&w1,    g_w1);
    cudaGetSymbolAddress((void**)&w2,    g_w2);

    constexpr int SMBIG = BigCfg::SMEM;    // 107520
    constexpr int SMF   = FuseCfg::SMEM;   // 77056
    cudaFuncSetAttribute((const void*)gemm_bf16_k<D_MODEL, 3 * D_MODEL, false, false>,
                         cudaFuncAttributeMaxDynamicSharedMemorySize, SMBIG);
    cudaFuncSetAttribute((const void*)gemm_bf16_k<D_MODEL, D_FF, true, true>,
                         cudaFuncAttributeMaxDynamicSharedMemorySize, SMBIG);
    cudaFuncSetAttribute((const void*)gemm_ln_fused<D_MODEL, true>,
                         cudaFuncAttributeMaxDynamicSharedMemorySize, SMF);
    cudaFuncSetAttribute((const void*)gemm_ln_fused<D_FF, false>,
                         cudaFuncAttributeMaxDynamicSharedMemorySize, SMF);

    cvt_kernel<<<Q_W2 / 256, 256>>>(x, qkv_w, out_w, ff_w1, ff_w2, xb, wq, wo, w1, w2);
    // QKV: N=768, 128x128 -> grid 6x48
    gemm_bf16_k<D_MODEL, 3 * D_MODEL, false, false><<<dim3(6, 48), 256, SMBIG>>>(xb, wq, qkv_b, qkv);
    attn_kernel<<<(N_TOK * N_HEADS) / 8, 256>>>(qkv, doc, attnb);
    // out-proj + residual(x) + LN1 -> x1 (fp32) and x1b (bf16); grid 192
    gemm_ln_fused<D_MODEL, true><<<192, 256, SMF>>>(attnb, wo, out_b, x, ln1_g, ln1_b, x1, x1b);
    // FF1: N=1024, 128x128 -> grid 8x48, gelu, bf16 out
    gemm_bf16_k<D_MODEL, D_FF, true, true><<<dim3(8, 48), 256, SMBIG>>>(x1b, w1, ff_b1, ffhb);
    // FF2 + residual(x1) + LN2 -> final out; grid 192
    gemm_ln_fused<D_FF, false><<<192, 256, SMF>>>(ffhb, w2, ff_b2, x1, ln2_g, ln2_b, out, nullptr);
}

// round 13
// speedup vs baseline: 1.0970x; 1.0970x over previous
#include <cuda_runtime.h>
#include <cuda_bf16.h>
#include <math.h>

#define N_TOK 6144
#define D_MODEL 256
#define N_HEADS 4
#define D_HEAD 64
#define D_FF 1024
#define LN_EPS 1e-5f

// ---------------- scratch (static device globals; no allocation) ----------------
__device__ float g_qkv [N_TOK * 3 * D_MODEL];           // fp32 (attention reads)
__device__ float g_x1  [N_TOK * D_MODEL];
__device__ float g_tmp [N_TOK * D_MODEL];
__device__ __nv_bfloat16 g_xb   [N_TOK * D_MODEL];      // bf16 activations/weights
__device__ __nv_bfloat16 g_attnb[N_TOK * D_MODEL];
__device__ __nv_bfloat16 g_x1b  [N_TOK * D_MODEL];
__device__ __nv_bfloat16 g_ffhb [N_TOK * D_FF];
__device__ __nv_bfloat16 g_wq   [D_MODEL * 3 * D_MODEL];
__device__ __nv_bfloat16 g_wo   [D_MODEL * D_MODEL];
__device__ __nv_bfloat16 g_w1   [D_MODEL * D_FF];
__device__ __nv_bfloat16 g_w2   [D_FF * D_MODEL];

// ---------------- helpers --------------------------------------------------------
__device__ __forceinline__ void cp16(void* smem_dst, const void* gsrc) {
    unsigned d = (unsigned)__cvta_generic_to_shared(smem_dst);
    asm volatile("cp.async.cg.shared.global [%0], [%1], 16;\n" :: "r"(d), "l"(gsrc));
}
__device__ __forceinline__ void cp_commit() { asm volatile("cp.async.commit_group;\n"); }
template<int NLEFT>
__device__ __forceinline__ void cp_wait()   { asm volatile("cp.async.wait_group %0;\n" :: "n"(NLEFT)); }

__device__ __forceinline__ void ldsm_x4(unsigned& r0, unsigned& r1, unsigned& r2, unsigned& r3,
                                        const void* p) {
    unsigned a = (unsigned)__cvta_generic_to_shared(p);
    asm volatile("ldmatrix.sync.aligned.m8n8.x4.shared.b16 {%0,%1,%2,%3}, [%4];"
                 : "=r"(r0), "=r"(r1), "=r"(r2), "=r"(r3) : "r"(a));
}
__device__ __forceinline__ void ldsm_x2t(unsigned& r0, unsigned& r1, const void* p) {
    unsigned a = (unsigned)__cvta_generic_to_shared(p);
    asm volatile("ldmatrix.sync.aligned.m8n8.x2.trans.shared.b16 {%0,%1}, [%2];"
                 : "=r"(r0), "=r"(r1) : "r"(a));
}
__device__ __forceinline__ void mma_bf16(
    float& c0, float& c1, float& c2, float& c3,
    unsigned a0, unsigned a1, unsigned a2, unsigned a3,
    unsigned b0, unsigned b1)
{
    asm volatile(
        "mma.sync.aligned.m16n8k16.row.col.f32.bf16.bf16.f32 "
        "{%0,%1,%2,%3}, {%4,%5,%6,%7}, {%8,%9}, {%0,%1,%2,%3};\n"
        : "+f"(c0), "+f"(c1), "+f"(c2), "+f"(c3)
        : "r"(a0), "r"(a1), "r"(a2), "r"(a3), "r"(b0), "r"(b1));
}

// Canonical PDL pattern: sync-then-trigger at kernel start. "This kernel
// launched" transitively implies all earlier kernels in the chain completed.
__device__ __forceinline__ void pdl_entry() {
    cudaGridDependencySynchronize();
    cudaTriggerProgrammaticLaunchCompletion();
}

// ---------------- bf16 tensor-core GEMM, BK=64, 3-stage cp.async pipeline --------
// Block tile BM x BN, 8 warps as 2(M) x 4(N). Warp tile (BM/2) x (BN/4).
// Small config (BM=BN=64) register-double-buffers ldmatrix fragments and runs
// 3 CTAs/SM; big config (128x128) runs 2 CTAs/SM.  (R10 internals, unchanged.)
#define BK 64
#define NSTG 3
#define A_STR 72    // 64 + 8 pad, words; stride 144B -> conflict-free ldmatrix

template<int BM, int BN> struct GemmCfg {
    static constexpr int B_STR = (BN == 128) ? 136 : 72;
    static constexpr int SMEM  = (NSTG * BM * A_STR + NSTG * BK * B_STR) * 2;
};

template<int K, int N, int BM, int BN, bool DOGELU, bool OUTBF16>
__global__ __launch_bounds__(256, (BM == 128) ? 2 : 3) void gemm_bf16_k(
    const __nv_bfloat16* __restrict__ A, const __nv_bfloat16* __restrict__ B,
    const float* __restrict__ bias, void* __restrict__ Cv)
{
    pdl_entry();

    constexpr int B_STR = GemmCfg<BM, BN>::B_STR;
    constexpr int WM = BM / 2;                 // 64 or 32
    constexpr int WN = BN / 4;                 // 32 or 16
    constexpr int MI = WM / 16;                // 4 or 2
    constexpr int NI = WN / 8;                 // 4 or 2
    constexpr int KS = BK / 16;                // 4
    constexpr bool DB = (MI * NI <= 4);        // frag double-buffer on small config

    extern __shared__ __nv_bfloat16 smdyn[];
    typedef __nv_bfloat16 (*AsT)[BM][A_STR];
    typedef __nv_bfloat16 (*BsT)[BK][B_STR];
    AsT As = reinterpret_cast<AsT>(smdyn);
    BsT Bs = reinterpret_cast<BsT>(smdyn + NSTG * BM * A_STR);

    const int tid  = threadIdx.x;
    const int row0 = blockIdx.y * BM;
    const int col0 = blockIdx.x * BN;
    const int w    = tid >> 5;
    const int lane = tid & 31;
    const int wm = w & 1;
    const int wn = w >> 1;
    const int g  = lane >> 2;
    const int t4 = lane & 3;

    float acc[MI][NI][4];
#pragma unroll
    for (int mi = 0; mi < MI; mi++)
#pragma unroll
        for (int ni = 0; ni < NI; ni++)
#pragma unroll
            for (int r = 0; r < 4; r++) acc[mi][ni][r] = 0.f;

    auto stage = [&](int kt, int buf) {
#pragma unroll
        for (int c = tid; c < BM * 8; c += 256) {           // A: BM x 64 / 8-elem chunks
            int r = c >> 3, col = (c & 7) * 8;
            cp16(&As[buf][r][col], A + (size_t)(row0 + r) * K + kt + col);
        }
#pragma unroll
        for (int c = tid; c < 8 * BN; c += 256) {           // B: 64 x BN / 8-elem chunks
            int r = c / (BN / 8), col = (c % (BN / 8)) * 8;
            cp16(&Bs[buf][r][col], B + (size_t)(kt + r) * N + col0 + col);
        }
        cp_commit();
    };

    constexpr int T = K / BK;
    static_assert(T >= 2, "need at least 2 k-slabs");
    stage(0, 0);
    stage(BK, 1);

    // ldmatrix lane addressing
    const int a_row = lane & 15;
    const int a_col = ((lane >> 4) << 3);
    const int b_row = lane & 15;

    auto load_frags = [&](unsigned (&af)[MI][4], unsigned (&bf)[NI][2], int buf, int ks) {
        const int kc = ks * 16;
#pragma unroll
        for (int mi = 0; mi < MI; mi++)
            ldsm_x4(af[mi][0], af[mi][1], af[mi][2], af[mi][3],
                    &As[buf][wm * WM + mi * 16 + a_row][kc + a_col]);
#pragma unroll
        for (int ni = 0; ni < NI; ni++)
            ldsm_x2t(bf[ni][0], bf[ni][1], &Bs[buf][kc + b_row][wn * WN + ni * 8]);
    };
    auto mma_all = [&](unsigned (&af)[MI][4], unsigned (&bf)[NI][2]) {
#pragma unroll
        for (int mi = 0; mi < MI; mi++)
#pragma unroll
            for (int ni = 0; ni < NI; ni++)
                mma_bf16(acc[mi][ni][0], acc[mi][ni][1], acc[mi][ni][2], acc[mi][ni][3],
                         af[mi][0], af[mi][1], af[mi][2], af[mi][3],
                         bf[ni][0], bf[ni][1]);
    };

    for (int t = 0; t < T; t++) {
        cp_wait<1>();            // slab t resident
        __syncthreads();
        if (t + 2 < T) stage((t + 2) * BK, (t + 2) % 3);
        else cp_commit();        // keep group count in lockstep
        const int buf = t % 3;

        if (DB) {
            unsigned af[2][MI][4], bf[2][NI][2];
            load_frags(af[0], bf[0], buf, 0);
#pragma unroll
            for (int ks = 0; ks < KS; ks++) {
                const int cur = ks & 1;
                if (ks + 1 < KS) load_frags(af[cur ^ 1], bf[cur ^ 1], buf, ks + 1);
                mma_all(af[cur], bf[cur]);
            }
        } else {
#pragma unroll
            for (int ks = 0; ks < KS; ks++) {
                unsigned af[MI][4], bf[NI][2];
                load_frags(af, bf, buf, ks);
                mma_all(af, bf);
            }
        }
    }

    // epilogue: bias (+gelu)
#pragma unroll
    for (int mi = 0; mi < MI; mi++) {
        const int r0g = row0 + wm * WM + mi * 16 + g;
#pragma unroll
        for (int ni = 0; ni < NI; ni++) {
            const int c = col0 + wn * WN + ni * 8 + t4 * 2;
            const float bx = bias[c], by = bias[c + 1];
            float v0 = acc[mi][ni][0] + bx, v1 = acc[mi][ni][1] + by;
            float v2 = acc[mi][ni][2] + bx, v3 = acc[mi][ni][3] + by;
            if (DOGELU) {
                v0 = 0.5f * v0 * (1.f + erff(v0 * 0.70710678118654752f));
                v1 = 0.5f * v1 * (1.f + erff(v1 * 0.70710678118654752f));
                v2 = 0.5f * v2 * (1.f + erff(v2 * 0.70710678118654752f));
                v3 = 0.5f * v3 * (1.f + erff(v3 * 0.70710678118654752f));
            }
            if (OUTBF16) {
                __nv_bfloat16* C = (__nv_bfloat16*)Cv;
                *reinterpret_cast<__nv_bfloat162*>(C + (size_t)r0g * N + c) =
                    __floats2bfloat162_rn(v0, v1);
                *reinterpret_cast<__nv_bfloat162*>(C + (size_t)(r0g + 8) * N + c) =
                    __floats2bfloat162_rn(v2, v3);
            } else {
                float* C = (float*)Cv;
                *reinterpret_cast<float2*>(C + (size_t)r0g * N + c)       = make_float2(v0, v1);
                *reinterpret_cast<float2*>(C + (size_t)(r0g + 8) * N + c) = make_float2(v2, v3);
            }
        }
    }
}

// ---------------- fp32 -> bf16 conversion of x + weights (one kernel) ------------
#define Q_X   393216           // 6144*256/4
#define Q_WQ  (Q_X  + 49152)   // 256*768/4
#define Q_WO  (Q_WQ + 16384)   // 256*256/4
#define Q_W1  (Q_WO + 65536)   // 256*1024/4
#define Q_W2  (Q_W1 + 65536)   // 1024*256/4  -> total 589824 quads
__global__ __launch_bounds__(256) void cvt_kernel(
    const float* __restrict__ x,  const float* __restrict__ wq,
    const float* __restrict__ wo, const float* __restrict__ w1,
    const float* __restrict__ w2,
    __nv_bfloat16* __restrict__ xb, __nv_bfloat16* __restrict__ wqb,
    __nv_bfloat16* __restrict__ wob, __nv_bfloat16* __restrict__ w1b,
    __nv_bfloat16* __restrict__ w2b)
{
    int q = blockIdx.x * 256 + threadIdx.x;
    const float* s; __nv_bfloat16* d; int base;
    if      (q < Q_X)  { s = x;  d = xb;  base = 0;    }
    else if (q < Q_WQ) { s = wq; d = wqb; base = Q_X;  }
    else if (q < Q_WO) { s = wo; d = wob; base = Q_WQ; }
    else if (q < Q_W1) { s = w1; d = w1b; base = Q_WO; }
    else               { s = w2; d = w2b; base = Q_W1; }
    size_t i = (size_t)(q - base) * 4;
    float4 v = *reinterpret_cast<const float4*>(s + i);
    reinterpret_cast<__nv_bfloat162*>(d + i)[0] = __floats2bfloat162_rn(v.x, v.y);
    reinterpret_cast<__nv_bfloat162*>(d + i)[1] = __floats2bfloat162_rn(v.z, v.w);
}

// ---------------- segment attention: one warp per (token, head), bf16 out -------
// Segment bounds via one coalesced 32-token window + ballot (doc idx is sorted);
// doc is a graph INPUT (no prior kernel writes it), so bounds are computed
// before the PDL grid sync; qkv (producer data) is only read after the sync.
__global__ __launch_bounds__(256) void attn_kernel(
    const float* __restrict__ qkv, const int* __restrict__ doc,
    __nv_bfloat16* __restrict__ out)
{
    int wg = (blockIdx.x * 256 + threadIdx.x) >> 5;
    int lane = threadIdx.x & 31;
    int i = wg >> 2;   // grid sized exactly: wg < N_TOK*N_HEADS always
    int h = wg & 3;

    const int my = doc[i];
    const int base = i - 16;
    const int idx = base + lane;
    int dv = -1;
    if (idx >= 0 && idx < N_TOK) dv = doc[idx];
    unsigned eq = __ballot_sync(0xffffffffu, dv == my);

    unsigned below = ~eq & 0xffffu;
    int s = (below == 0) ? base : base + (32 - __clz(below));
    unsigned above = ~eq & 0xfffe0000u;
    int e = (above == 0) ? base + 32 : base + (__ffs(above) - 1);
    if (below == 0) { while (s > 0 && doc[s - 1] == my) s--; }
    if (above == 0) { while (e < N_TOK && doc[e] == my) e++; }

    pdl_entry();     // qkv (producer data) is read only below this point

    const float* q = qkv + (size_t)i * (3 * D_MODEL) + h * D_HEAD;
    float q0 = q[lane], q1 = q[lane + 32];
    const float* kbase = qkv + D_MODEL + h * D_HEAD;
    const float* vbase = qkv + 2 * D_MODEL + h * D_HEAD;

    float m = -3.4e38f, sum = 0.f, o0 = 0.f, o1 = 0.f;
    for (int j = s; j < e; j++) {
        const float* kr = kbase + (size_t)j * (3 * D_MODEL);
        float d = q0 * kr[lane] + q1 * kr[lane + 32];
#pragma unroll
        for (int off = 16; off; off >>= 1) d += __shfl_xor_sync(0xffffffffu, d, off);
        float sc = d * 0.125f;
        float mn = fmaxf(m, sc);
        float corr = __expf(m - mn);
        float p = __expf(sc - mn);
        const float* vr = vbase + (size_t)j * (3 * D_MODEL);
        sum = sum * corr + p;
        o0 = o0 * corr + p * vr[lane];
        o1 = o1 * corr + p * vr[lane + 32];
        m = mn;
    }
    float inv = 1.f / sum;
    out[(size_t)i * D_MODEL + h * D_HEAD + lane]      = __float2bfloat16(o0 * inv);
    out[(size_t)i * D_MODEL + h * D_HEAD + lane + 32] = __float2bfloat16(o1 * inv);
}

// ---------------- residual + layernorm: warp per row; optional bf16 dual write --
template<bool DUAL>
__global__ __launch_bounds__(256) void ln_kernel(
    const float* __restrict__ y, const float* __restrict__ res,
    const float* __restrict__ gw, const float* __restrict__ bw,
    float* __restrict__ out, __nv_bfloat16* __restrict__ outb)
{
    pdl_entry();
    int row = blockIdx.x * 8 + (threadIdx.x >> 5);
    int lane = threadIdx.x & 31;
    size_t base = (size_t)row * D_MODEL;

    float4 a0 = *reinterpret_cast<const float4*>(y + base + lane * 4);
    float4 r0 = *reinterpret_cast<const float4*>(res + base + lane * 4);
    float4 a1 = *reinterpret_cast<const float4*>(y + base + 128 + lane * 4);
    float4 r1 = *reinterpret_cast<const float4*>(res + base + 128 + lane * 4);
    a0.x += r0.x; a0.y += r0.y; a0.z += r0.z; a0.w += r0.w;
    a1.x += r1.x; a1.y += r1.y; a1.z += r1.z; a1.w += r1.w;

    float s  = a0.x + a0.y + a0.z + a0.w + a1.x + a1.y + a1.z + a1.w;
    float sq = a0.x*a0.x + a0.y*a0.y + a0.z*a0.z + a0.w*a0.w
             + a1.x*a1.x + a1.y*a1.y + a1.z*a1.z + a1.w*a1.w;
#pragma unroll
    for (int o = 16; o; o >>= 1) {
        s  += __shfl_xor_sync(0xffffffffu, s, o);
        sq += __shfl_xor_sync(0xffffffffu, sq, o);
    }
    float mu  = s * (1.f / D_MODEL);
    float var = sq * (1.f / D_MODEL) - mu * mu;
    float inv = rsqrtf(var + LN_EPS);

    float4 g0 = *reinterpret_cast<const float4*>(gw + lane * 4);
    float4 b0 = *reinterpret_cast<const float4*>(bw + lane * 4);
    float4 g1 = *reinterpret_cast<const float4*>(gw + 128 + lane * 4);
    float4 b1 = *reinterpret_cast<const float4*>(bw + 128 + lane * 4);
    float4 o0, o1;
    o0.x = (a0.x - mu) * inv * g0.x + b0.x;
    o0.y = (a0.y - mu) * inv * g0.y + b0.y;
    o0.z = (a0.z - mu) * inv * g0.z + b0.z;
    o0.w = (a0.w - mu) * inv * g0.w + b0.w;
    o1.x = (a1.x - mu) * inv * g1.x + b1.x;
    o1.y = (a1.y - mu) * inv * g1.y + b1.y;
    o1.z = (a1.z - mu) * inv * g1.z + b1.z;
    o1.w = (a1.w - mu) * inv * g1.w + b1.w;
    *reinterpret_cast<float4*>(out + base + lane * 4)       = o0;
    *reinterpret_cast<float4*>(out + base + 128 + lane * 4) = o1;
    if (DUAL) {
        reinterpret_cast<__nv_bfloat162*>(outb + base + lane * 4)[0] = __floats2bfloat162_rn(o0.x, o0.y);
        reinterpret_cast<__nv_bfloat162*>(outb + base + lane * 4)[1] = __floats2bfloat162_rn(o0.z, o0.w);
        reinterpret_cast<__nv_bfloat162*>(outb + base + 128 + lane * 4)[0] = __floats2bfloat162_rn(o1.x, o1.y);
        reinterpret_cast<__nv_bfloat162*>(outb + base + 128 + lane * 4)[1] = __floats2bfloat162_rn(o1.z, o1.w);
    }
}

// ---------------- PDL launch helper ----------------------------------------------
template<typename F, typename... Args>
static inline void launch_pdl(F* f, dim3 grid, dim3 block, size_t smem, Args... args) {
    cudaLaunchConfig_t cfg = {};
    cfg.gridDim = grid;
    cfg.blockDim = block;
    cfg.dynamicSmemBytes = smem;
    cfg.stream = 0;
    cudaLaunchAttribute at[1];
    at[0].id = cudaLaunchAttributeProgrammaticStreamSerialization;
    at[0].val.programmaticStreamSerializationAllowed = 1;
    cfg.attrs = at;
    cfg.numAttrs = 1;
    cudaLaunchKernelEx(&cfg, f, args...);
}

// ---------------- launch ---------------------------------------------------------
extern "C" void kernel_launch(void* const* d_in, const int* in_sizes, int n_in,
                              void* d_out, int out_size)
{
    const float* x      = (const float*)d_in[0];
    const int*   doc    = (const int*)  d_in[1];
    const float* qkv_w  = (const float*)d_in[2];
    const float* qkv_b  = (const float*)d_in[3];
    const float* out_w  = (const float*)d_in[4];
    const float* out_b  = (const float*)d_in[5];
    const float* ff_w1  = (const float*)d_in[6];
    const float* ff_b1  = (const float*)d_in[7];
    const float* ff_w2  = (const float*)d_in[8];
    const float* ff_b2  = (const float*)d_in[9];
    const float* ln1_g  = (const float*)d_in[10];
    const float* ln1_b  = (const float*)d_in[11];
    const float* ln2_g  = (const float*)d_in[12];
    const float* ln2_b  = (const float*)d_in[13];
    float* out = (float*)d_out;

    float *qkv, *x1, *tmp;
    __nv_bfloat16 *xb, *attnb, *x1b, *ffhb, *wq, *wo, *w1, *w2;
    cudaGetSymbolAddress((void**)&qkv,   g_qkv);
    cudaGetSymbolAddress((void**)&x1,    g_x1);
    cudaGetSymbolAddress((void**)&tmp,   g_tmp);
    cudaGetSymbolAddress((void**)&xb,    g_xb);
    cudaGetSymbolAddress((void**)&attnb, g_attnb);
    cudaGetSymbolAddress((void**)&x1b,   g_x1b);
    cudaGetSymbolAddress((void**)&ffhb,  g_ffhb);
    cudaGetSymbolAddress((void**)&wq,    g_wq);
    cudaGetSymbolAddress((void**)&wo,    g_wo);
    cudaGetSymbolAddress((void**)&w1,    g_w1);
    cudaGetSymbolAddress((void**)&w2,    g_w2);

    // opt-in to >48KB dynamic smem (idempotent host-side attribute sets)
    constexpr int SMBIG = GemmCfg<128, 128>::SMEM;   // 107520
    constexpr int SMSML = GemmCfg<64, 64>::SMEM;     // 55296
    auto* kQKV = gemm_bf16_k<D_MODEL, 3 * D_MODEL, 128, 128, false, false>;
    auto* kOP  = gemm_bf16_k<D_MODEL, D_MODEL, 64, 64, false, false>;
    auto* kFF1 = gemm_bf16_k<D_MODEL, D_FF, 128, 128, true, true>;
    auto* kFF2 = gemm_bf16_k<D_FF, D_MODEL, 64, 64, false, false>;
    cudaFuncSetAttribute((const void*)kQKV, cudaFuncAttributeMaxDynamicSharedMemorySize, SMBIG);
    cudaFuncSetAttribute((const void*)kFF1, cudaFuncAttributeMaxDynamicSharedMemorySize, SMBIG);
    cudaFuncSetAttribute((const void*)kOP,  cudaFuncAttributeMaxDynamicSharedMemorySize, SMSML);
    cudaFuncSetAttribute((const void*)kFF2, cudaFuncAttributeMaxDynamicSharedMemorySize, SMSML);

    // 1. fp32->bf16 conversions (first kernel; plain launch, implicit trigger at end)
    cvt_kernel<<<Q_W2 / 256, 256>>>(x, qkv_w, out_w, ff_w1, ff_w2, xb, wq, wo, w1, w2);
    // 2. QKV: N=768, 128x128 -> grid 6x48
    launch_pdl(kQKV, dim3(6, 48), dim3(256), (size_t)SMBIG,
               (const __nv_bfloat16*)xb, (const __nv_bfloat16*)wq, qkv_b, (void*)qkv);
    // 3. segment attention
    launch_pdl(attn_kernel, dim3((N_TOK * N_HEADS) / 8), dim3(256), (size_t)0,
               (const float*)qkv, doc, attnb);
    // 4. out-proj: N=256, 64x64 -> grid 4x96
    launch_pdl(kOP, dim3(4, 96), dim3(256), (size_t)SMSML,
               (const __nv_bfloat16*)attnb, (const __nv_bfloat16*)wo, out_b, (void*)tmp);
    // 5. x1 = LN(x + proj), dual write fp32 + bf16
    launch_pdl(ln_kernel<true>, dim3(N_TOK / 8), dim3(256), (size_t)0,
               (const float*)tmp, x, ln1_g, ln1_b, x1, x1b);
    // 6. FF1: N=1024, 128x128 -> grid 8x48, gelu, bf16 out
    launch_pdl(kFF1, dim3(8, 48), dim3(256), (size_t)SMBIG,
               (const __nv_bfloat16*)x1b, (const __nv_bfloat16*)w1, ff_b1, (void*)ffhb);
    // 7. FF2: N=256, 64x64 -> grid 4x96
    launch_pdl(kFF2, dim3(4, 96), dim3(256), (size_t)SMSML,
               (const __nv_bfloat16*)ffhb, (const __nv_bfloat16*)w2, ff_b2, (void*)tmp);
    // 8. out = LN(x1 + ff)
    launch_pdl(ln_kernel<false>, dim3(N_TOK / 8), dim3(256), (size_t)0,
               (const float*)tmp, (const float*)x1, ln2_g, ln2_b, out, (__nv_bfloat16*)nullptr);
}

// round 14
// speedup vs baseline: 1.1437x; 1.0426x over previous
#include <cuda_runtime.h>
#include <cuda_bf16.h>
#include <math.h>

#define N_TOK 6144
#define D_MODEL 256
#define N_HEADS 4
#define D_HEAD 64
#define D_FF 1024
#define LN_EPS 1e-5f

// ---------------- scratch (static device globals; no allocation) ----------------
__device__ float g_qkv [N_TOK * 3 * D_MODEL];           // fp32 (attention reads)
__device__ float g_x1  [N_TOK * D_MODEL];
__device__ float g_tmp [N_TOK * D_MODEL];
__device__ __nv_bfloat16 g_xb   [N_TOK * D_MODEL];      // bf16 activations/weights
__device__ __nv_bfloat16 g_attnb[N_TOK * D_MODEL];
__device__ __nv_bfloat16 g_x1b  [N_TOK * D_MODEL];
__device__ __nv_bfloat16 g_ffhb [N_TOK * D_FF];
__device__ __nv_bfloat16 g_wq   [D_MODEL * 3 * D_MODEL];
__device__ __nv_bfloat16 g_wo   [D_MODEL * D_MODEL];
__device__ __nv_bfloat16 g_w1   [D_MODEL * D_FF];
__device__ __nv_bfloat16 g_w2   [D_FF * D_MODEL];

// ---------------- helpers --------------------------------------------------------
__device__ __forceinline__ void cp16(void* smem_dst, const void* gsrc) {
    unsigned d = (unsigned)__cvta_generic_to_shared(smem_dst);
    asm volatile("cp.async.cg.shared.global [%0], [%1], 16;\n" :: "r"(d), "l"(gsrc));
}
__device__ __forceinline__ void cp_commit() { asm volatile("cp.async.commit_group;\n"); }
template<int NLEFT>
__device__ __forceinline__ void cp_wait()   { asm volatile("cp.async.wait_group %0;\n" :: "n"(NLEFT)); }

__device__ __forceinline__ void ldsm_x4(unsigned& r0, unsigned& r1, unsigned& r2, unsigned& r3,
                                        const void* p) {
    unsigned a = (unsigned)__cvta_generic_to_shared(p);
    asm volatile("ldmatrix.sync.aligned.m8n8.x4.shared.b16 {%0,%1,%2,%3}, [%4];"
                 : "=r"(r0), "=r"(r1), "=r"(r2), "=r"(r3) : "r"(a));
}
__device__ __forceinline__ void ldsm_x2t(unsigned& r0, unsigned& r1, const void* p) {
    unsigned a = (unsigned)__cvta_generic_to_shared(p);
    asm volatile("ldmatrix.sync.aligned.m8n8.x2.trans.shared.b16 {%0,%1}, [%2];"
                 : "=r"(r0), "=r"(r1) : "r"(a));
}
__device__ __forceinline__ void mma_bf16(
    float& c0, float& c1, float& c2, float& c3,
    unsigned a0, unsigned a1, unsigned a2, unsigned a3,
    unsigned b0, unsigned b1)
{
    asm volatile(
        "mma.sync.aligned.m16n8k16.row.col.f32.bf16.bf16.f32 "
        "{%0,%1,%2,%3}, {%4,%5,%6,%7}, {%8,%9}, {%0,%1,%2,%3};\n"
        : "+f"(c0), "+f"(c1), "+f"(c2), "+f"(c3)
        : "r"(a0), "r"(a1), "r"(a2), "r"(a3), "r"(b0), "r"(b1));
}

// Canonical PDL pattern: sync-then-trigger at kernel start.
__device__ __forceinline__ void pdl_entry() {
    cudaGridDependencySynchronize();
    cudaTriggerProgrammaticLaunchCompletion();
}

// ---------------- bf16 tensor-core GEMM, BK=64, 3-stage cp.async pipeline --------
// (R10/R13 internals, unchanged.)
#define BK 64
#define NSTG 3
#define A_STR 72    // 64 + 8 pad, words; stride 144B -> conflict-free ldmatrix

template<int BM, int BN> struct GemmCfg {
    static constexpr int B_STR = (BN == 128) ? 136 : 72;
    static constexpr int SMEM  = (NSTG * BM * A_STR + NSTG * BK * B_STR) * 2;
};

template<int K, int N, int BM, int BN, bool DOGELU, bool OUTBF16>
__global__ __launch_bounds__(256, (BM == 128) ? 2 : 3) void gemm_bf16_k(
    const __nv_bfloat16* __restrict__ A, const __nv_bfloat16* __restrict__ B,
    const float* __restrict__ bias, void* __restrict__ Cv)
{
    pdl_entry();

    constexpr int B_STR = GemmCfg<BM, BN>::B_STR;
    constexpr int WM = BM / 2;
    constexpr int WN = BN / 4;
    constexpr int MI = WM / 16;
    constexpr int NI = WN / 8;
    constexpr int KS = BK / 16;
    constexpr bool DB = (MI * NI <= 4);

    extern __shared__ __nv_bfloat16 smdyn[];
    typedef __nv_bfloat16 (*AsT)[BM][A_STR];
    typedef __nv_bfloat16 (*BsT)[BK][B_STR];
    AsT As = reinterpret_cast<AsT>(smdyn);
    BsT Bs = reinterpret_cast<BsT>(smdyn + NSTG * BM * A_STR);

    const int tid  = threadIdx.x;
    const int row0 = blockIdx.y * BM;
    const int col0 = blockIdx.x * BN;
    const int w    = tid >> 5;
    const int lane = tid & 31;
    const int wm = w & 1;
    const int wn = w >> 1;
    const int g  = lane >> 2;
    const int t4 = lane & 3;

    float acc[MI][NI][4];
#pragma unroll
    for (int mi = 0; mi < MI; mi++)
#pragma unroll
        for (int ni = 0; ni < NI; ni++)
#pragma unroll
            for (int r = 0; r < 4; r++) acc[mi][ni][r] = 0.f;

    auto stage = [&](int kt, int buf) {
#pragma unroll
        for (int c = tid; c < BM * 8; c += 256) {
            int r = c >> 3, col = (c & 7) * 8;
            cp16(&As[buf][r][col], A + (size_t)(row0 + r) * K + kt + col);
        }
#pragma unroll
        for (int c = tid; c < 8 * BN; c += 256) {
            int r = c / (BN / 8), col = (c % (BN / 8)) * 8;
            cp16(&Bs[buf][r][col], B + (size_t)(kt + r) * N + col0 + col);
        }
        cp_commit();
    };

    constexpr int T = K / BK;
    static_assert(T >= 2, "need at least 2 k-slabs");
    stage(0, 0);
    stage(BK, 1);

    const int a_row = lane & 15;
    const int a_col = ((lane >> 4) << 3);
    const int b_row = lane & 15;

    auto load_frags = [&](unsigned (&af)[MI][4], unsigned (&bf)[NI][2], int buf, int ks) {
        const int kc = ks * 16;
#pragma unroll
        for (int mi = 0; mi < MI; mi++)
            ldsm_x4(af[mi][0], af[mi][1], af[mi][2], af[mi][3],
                    &As[buf][wm * WM + mi * 16 + a_row][kc + a_col]);
#pragma unroll
        for (int ni = 0; ni < NI; ni++)
            ldsm_x2t(bf[ni][0], bf[ni][1], &Bs[buf][kc + b_row][wn * WN + ni * 8]);
    };
    auto mma_all = [&](unsigned (&af)[MI][4], unsigned (&bf)[NI][2]) {
#pragma unroll
        for (int mi = 0; mi < MI; mi++)
#pragma unroll
            for (int ni = 0; ni < NI; ni++)
                mma_bf16(acc[mi][ni][0], acc[mi][ni][1], acc[mi][ni][2], acc[mi][ni][3],
                         af[mi][0], af[mi][1], af[mi][2], af[mi][3],
                         bf[ni][0], bf[ni][1]);
    };

    for (int t = 0; t < T; t++) {
        cp_wait<1>();
        __syncthreads();
        if (t + 2 < T) stage((t + 2) * BK, (t + 2) % 3);
        else cp_commit();
        const int buf = t % 3;

        if (DB) {
            unsigned af[2][MI][4], bf[2][NI][2];
            load_frags(af[0], bf[0], buf, 0);
#pragma unroll
            for (int ks = 0; ks < KS; ks++) {
                const int cur = ks & 1;
                if (ks + 1 < KS) load_frags(af[cur ^ 1], bf[cur ^ 1], buf, ks + 1);
                mma_all(af[cur], bf[cur]);
            }
        } else {
#pragma unroll
            for (int ks = 0; ks < KS; ks++) {
                unsigned af[MI][4], bf[NI][2];
                load_frags(af, bf, buf, ks);
                mma_all(af, bf);
            }
        }
    }

    // epilogue: bias (+gelu)
#pragma unroll
    for (int mi = 0; mi < MI; mi++) {
        const int r0g = row0 + wm * WM + mi * 16 + g;
#pragma unroll
        for (int ni = 0; ni < NI; ni++) {
            const int c = col0 + wn * WN + ni * 8 + t4 * 2;
            const float bx = bias[c], by = bias[c + 1];
            float v0 = acc[mi][ni][0] + bx, v1 = acc[mi][ni][1] + by;
            float v2 = acc[mi][ni][2] + bx, v3 = acc[mi][ni][3] + by;
            if (DOGELU) {
                v0 = 0.5f * v0 * (1.f + erff(v0 * 0.70710678118654752f));
                v1 = 0.5f * v1 * (1.f + erff(v1 * 0.70710678118654752f));
                v2 = 0.5f * v2 * (1.f + erff(v2 * 0.70710678118654752f));
                v3 = 0.5f * v3 * (1.f + erff(v3 * 0.70710678118654752f));
            }
            if (OUTBF16) {
                __nv_bfloat16* C = (__nv_bfloat16*)Cv;
                *reinterpret_cast<__nv_bfloat162*>(C + (size_t)r0g * N + c) =
                    __floats2bfloat162_rn(v0, v1);
                *reinterpret_cast<__nv_bfloat162*>(C + (size_t)(r0g + 8) * N + c) =
                    __floats2bfloat162_rn(v2, v3);
            } else {
                float* C = (float*)Cv;
                *reinterpret_cast<float2*>(C + (size_t)r0g * N + c)       = make_float2(v0, v1);
                *reinterpret_cast<float2*>(C + (size_t)(r0g + 8) * N + c) = make_float2(v2, v3);
            }
        }
    }
}

// ---------------- fp32 -> bf16 conversion of x + weights (one kernel) ------------
#define Q_X   393216           // 6144*256/4
#define Q_WQ  (Q_X  + 49152)   // 256*768/4
#define Q_WO  (Q_WQ + 16384)   // 256*256/4
#define Q_W1  (Q_WO + 65536)   // 256*1024/4
#define Q_W2  (Q_W1 + 65536)   // 1024*256/4  -> total 589824 quads
__global__ __launch_bounds__(256) void cvt_kernel(
    const float* __restrict__ x,  const float* __restrict__ wq,
    const float* __restrict__ wo, const float* __restrict__ w1,
    const float* __restrict__ w2,
    __nv_bfloat16* __restrict__ xb, __nv_bfloat16* __restrict__ wqb,
    __nv_bfloat16* __restrict__ wob, __nv_bfloat16* __restrict__ w1b,
    __nv_bfloat16* __restrict__ w2b)
{
    int q = blockIdx.x * 256 + threadIdx.x;
    const float* s; __nv_bfloat16* d; int base;
    if      (q < Q_X)  { s = x;  d = xb;  base = 0;    }
    else if (q < Q_WQ) { s = wq; d = wqb; base = Q_X;  }
    else if (q < Q_WO) { s = wo; d = wob; base = Q_WQ; }
    else if (q < Q_W1) { s = w1; d = w1b; base = Q_WO; }
    else               { s = w2; d = w2b; base = Q_W1; }
    size_t i = (size_t)(q - base) * 4;
    float4 v = *reinterpret_cast<const float4*>(s + i);
    reinterpret_cast<__nv_bfloat162*>(d + i)[0] = __floats2bfloat162_rn(v.x, v.y);
    reinterpret_cast<__nv_bfloat162*>(d + i)[1] = __floats2bfloat162_rn(v.z, v.w);
}

// ---------------- segment attention: one warp per TOKEN, 4 heads in-lane --------
// Lane layout: h = lane>>3 (head), sub = lane&7 (8 dims of 64 per lane).
// Per key j: 4x ld.128 covers full 256-dim K and V rows once; dot reduced in
// 3 xor-shuffles within the 8-lane group (4 heads simultaneously); online
// softmax per group; V accumulated in-lane. Segment bounds via ballot over a
// 32-token window (doc sorted), scalar fallback for long segments.
__global__ __launch_bounds__(256) void attn_kernel(
    const float* __restrict__ qkv, const int* __restrict__ doc,
    __nv_bfloat16* __restrict__ out)
{
    const int i    = blockIdx.x * 8 + (threadIdx.x >> 5);   // token (grid sized exactly)
    const int lane = threadIdx.x & 31;
    const int h    = lane >> 3;
    const int sub  = lane & 7;
    const int doff = h * D_HEAD + sub * 8;                  // this lane's 8 dims

    const int my = doc[i];
    const int base = i - 16;
    const int idx = base + lane;
    int dv = -1;
    if (idx >= 0 && idx < N_TOK) dv = doc[idx];
    unsigned eq = __ballot_sync(0xffffffffu, dv == my);

    unsigned below = ~eq & 0xffffu;
    int s = (below == 0) ? base : base + (32 - __clz(below));
    unsigned above = ~eq & 0xfffe0000u;
    int e = (above == 0) ? base + 32 : base + (__ffs(above) - 1);
    if (below == 0) { while (s > 0 && doc[s - 1] == my) s--; }
    if (above == 0) { while (e < N_TOK && doc[e] == my) e++; }

    pdl_entry();     // qkv (producer data) read only below this point

    float4 q0 = *reinterpret_cast<const float4*>(qkv + (size_t)i * (3 * D_MODEL) + doff);
    float4 q1 = *reinterpret_cast<const float4*>(qkv + (size_t)i * (3 * D_MODEL) + doff + 4);

    const float* kbase = qkv + D_MODEL + doff;
    const float* vbase = qkv + 2 * D_MODEL + doff;

    float m = -3.4e38f, sum = 0.f;
    float o[8];
#pragma unroll
    for (int t = 0; t < 8; t++) o[t] = 0.f;

    for (int j = s; j < e; j++) {
        const size_t roff = (size_t)j * (3 * D_MODEL);
        float4 k0 = *reinterpret_cast<const float4*>(kbase + roff);
        float4 k1 = *reinterpret_cast<const float4*>(kbase + roff + 4);
        float d = q0.x * k0.x + q0.y * k0.y + q0.z * k0.z + q0.w * k0.w
                + q1.x * k1.x + q1.y * k1.y + q1.z * k1.z + q1.w * k1.w;
        // reduce within 8-lane group (xor-closed): 4 heads reduced at once
        d += __shfl_xor_sync(0xffffffffu, d, 1);
        d += __shfl_xor_sync(0xffffffffu, d, 2);
        d += __shfl_xor_sync(0xffffffffu, d, 4);
        float sc = d * 0.125f;                  // 1/sqrt(64)
        float mn = fmaxf(m, sc);
        float corr = __expf(m - mn);
        float p = __expf(sc - mn);
        float4 v0 = *reinterpret_cast<const float4*>(vbase + roff);
        float4 v1 = *reinterpret_cast<const float4*>(vbase + roff + 4);
        o[0] = o[0] * corr + p * v0.x;
        o[1] = o[1] * corr + p * v0.y;
        o[2] = o[2] * corr + p * v0.z;
        o[3] = o[3] * corr + p * v0.w;
        o[4] = o[4] * corr + p * v1.x;
        o[5] = o[5] * corr + p * v1.y;
        o[6] = o[6] * corr + p * v1.z;
        o[7] = o[7] * corr + p * v1.w;
        sum = sum * corr + p;
        m = mn;
    }
    float inv = 1.f / sum;
    __nv_bfloat162 r[4];
#pragma unroll
    for (int t = 0; t < 4; t++)
        r[t] = __floats2bfloat162_rn(o[2 * t] * inv, o[2 * t + 1] * inv);
    *reinterpret_cast<uint4*>(out + (size_t)i * D_MODEL + doff) =
        *reinterpret_cast<const uint4*>(r);
}

// ---------------- residual + layernorm: warp per row; optional bf16 dual write --
template<bool DUAL>
__global__ __launch_bounds__(256) void ln_kernel(
    const float* __restrict__ y, const float* __restrict__ res,
    const float* __restrict__ gw, const float* __restrict__ bw,
    float* __restrict__ out, __nv_bfloat16* __restrict__ outb)
{
    pdl_entry();
    int row = blockIdx.x * 8 + (threadIdx.x >> 5);
    int lane = threadIdx.x & 31;
    size_t base = (size_t)row * D_MODEL;

    float4 a0 = *reinterpret_cast<const float4*>(y + base + lane * 4);
    float4 r0 = *reinterpret_cast<const float4*>(res + base + lane * 4);
    float4 a1 = *reinterpret_cast<const float4*>(y + base + 128 + lane * 4);
    float4 r1 = *reinterpret_cast<const float4*>(res + base + 128 + lane * 4);
    a0.x += r0.x; a0.y += r0.y; a0.z += r0.z; a0.w += r0.w;
    a1.x += r1.x; a1.y += r1.y; a1.z += r1.z; a1.w += r1.w;

    float s  = a0.x + a0.y + a0.z + a0.w + a1.x + a1.y + a1.z + a1.w;
    float sq = a0.x*a0.x + a0.y*a0.y + a0.z*a0.z + a0.w*a0.w
             + a1.x*a1.x + a1.y*a1.y + a1.z*a1.z + a1.w*a1.w;
#pragma unroll
    for (int o = 16; o; o >>= 1) {
        s  += __shfl_xor_sync(0xffffffffu, s, o);
        sq += __shfl_xor_sync(0xffffffffu, sq, o);
    }
    float mu  = s * (1.f / D_MODEL);
    float var = sq * (1.f / D_MODEL) - mu * mu;
    float inv = rsqrtf(var + LN_EPS);

    float4 g0 = *reinterpret_cast<const float4*>(gw + lane * 4);
    float4 b0 = *reinterpret_cast<const float4*>(bw + lane * 4);
    float4 g1 = *reinterpret_cast<const float4*>(gw + 128 + lane * 4);
    float4 b1 = *reinterpret_cast<const float4*>(bw + 128 + lane * 4);
    float4 o0, o1;
    o0.x = (a0.x - mu) * inv * g0.x + b0.x;
    o0.y = (a0.y - mu) * inv * g0.y + b0.y;
    o0.z = (a0.z - mu) * inv * g0.z + b0.z;
    o0.w = (a0.w - mu) * inv * g0.w + b0.w;
    o1.x = (a1.x - mu) * inv * g1.x + b1.x;
    o1.y = (a1.y - mu) * inv * g1.y + b1.y;
    o1.z = (a1.z - mu) * inv * g1.z + b1.z;
    o1.w = (a1.w - mu) * inv * g1.w + b1.w;
    *reinterpret_cast<float4*>(out + base + lane * 4)       = o0;
    *reinterpret_cast<float4*>(out + base + 128 + lane * 4) = o1;
    if (DUAL) {
        reinterpret_cast<__nv_bfloat162*>(outb + base + lane * 4)[0] = __floats2bfloat162_rn(o0.x, o0.y);
        reinterpret_cast<__nv_bfloat162*>(outb + base + lane * 4)[1] = __floats2bfloat162_rn(o0.z, o0.w);
        reinterpret_cast<__nv_bfloat162*>(outb + base + 128 + lane * 4)[0] = __floats2bfloat162_rn(o1.x, o1.y);
        reinterpret_cast<__nv_bfloat162*>(outb + base + 128 + lane * 4)[1] = __floats2bfloat162_rn(o1.z, o1.w);
    }
}

// ---------------- PDL launch helper ----------------------------------------------
template<typename F, typename... Args>
static inline void launch_pdl(F* f, dim3 grid, dim3 block, size_t smem, Args... args) {
    cudaLaunchConfig_t cfg = {};
    cfg.gridDim = grid;
    cfg.blockDim = block;
    cfg.dynamicSmemBytes = smem;
    cfg.stream = 0;
    cudaLaunchAttribute at[1];
    at[0].id = cudaLaunchAttributeProgrammaticStreamSerialization;
    at[0].val.programmaticStreamSerializationAllowed = 1;
    cfg.attrs = at;
    cfg.numAttrs = 1;
    cudaLaunchKernelEx(&cfg, f, args...);
}

// ---------------- launch ---------------------------------------------------------
extern "C" void kernel_launch(void* const* d_in, const int* in_sizes, int n_in,
                              void* d_out, int out_size)
{
    const float* x      = (const float*)d_in[0];
    const int*   doc    = (const int*)  d_in[1];
    const float* qkv_w  = (const float*)d_in[2];
    const float* qkv_b  = (const float*)d_in[3];
    const float* out_w  = (const float*)d_in[4];
    const float* out_b  = (const float*)d_in[5];
    const float* ff_w1  = (const float*)d_in[6];
    const float* ff_b1  = (const float*)d_in[7];
    const float* ff_w2  = (const float*)d_in[8];
    const float* ff_b2  = (const float*)d_in[9];
    const float* ln1_g  = (const float*)d_in[10];
    const float* ln1_b  = (const float*)d_in[11];
    const float* ln2_g  = (const float*)d_in[12];
    const float* ln2_b  = (const float*)d_in[13];
    float* out = (float*)d_out;

    float *qkv, *x1, *tmp;
    __nv_bfloat16 *xb, *attnb, *x1b, *ffhb, *wq, *wo, *w1, *w2;
    cudaGetSymbolAddress((void**)&qkv,   g_qkv);
    cudaGetSymbolAddress((void**)&x1,    g_x1);
    cudaGetSymbolAddress((void**)&tmp,   g_tmp);
    cudaGetSymbolAddress((void**)&xb,    g_xb);
    cudaGetSymbolAddress((void**)&attnb, g_attnb);
    cudaGetSymbolAddress((void**)&x1b,   g_x1b);
    cudaGetSymbolAddress((void**)&ffhb,  g_ffhb);
    cudaGetSymbolAddress((void**)&wq,    g_wq);
    cudaGetSymbolAddress((void**)&wo,    g_wo);
    cudaGetSymbolAddress((void**)&w1,    g_w1);
    cudaGetSymbolAddress((void**)&w2,    g_w2);

    // opt-in to >48KB dynamic smem (idempotent host-side attribute sets)
    constexpr int SMBIG = GemmCfg<128, 128>::SMEM;   // 107520
    constexpr int SMSML = GemmCfg<64, 64>::SMEM;     // 55296
    auto* kQKV = gemm_bf16_k<D_MODEL, 3 * D_MODEL, 128, 128, false, false>;
    auto* kOP  = gemm_bf16_k<D_MODEL, D_MODEL, 64, 64, false, false>;
    auto* kFF1 = gemm_bf16_k<D_MODEL, D_FF, 128, 128, true, true>;
    auto* kFF2 = gemm_bf16_k<D_FF, D_MODEL, 64, 64, false, false>;
    cudaFuncSetAttribute((const void*)kQKV, cudaFuncAttributeMaxDynamicSharedMemorySize, SMBIG);
    cudaFuncSetAttribute((const void*)kFF1, cudaFuncAttributeMaxDynamicSharedMemorySize, SMBIG);
    cudaFuncSetAttribute((const void*)kOP,  cudaFuncAttributeMaxDynamicSharedMemorySize, SMSML);
    cudaFuncSetAttribute((const void*)kFF2, cudaFuncAttributeMaxDynamicSharedMemorySize, SMSML);

    // 1. fp32->bf16 conversions (first kernel; plain launch)
    cvt_kernel<<<Q_W2 / 256, 256>>>(x, qkv_w, out_w, ff_w1, ff_w2, xb, wq, wo, w1, w2);
    // 2. QKV: N=768, 128x128 -> grid 6x48
    launch_pdl(kQKV, dim3(6, 48), dim3(256), (size_t)SMBIG,
               (const __nv_bfloat16*)xb, (const __nv_bfloat16*)wq, qkv_b, (void*)qkv);
    // 3. segment attention: warp per token -> 6144/8 = 768 CTAs
    launch_pdl(attn_kernel, dim3(N_TOK / 8), dim3(256), (size_t)0,
               (const float*)qkv, doc, attnb);
    // 4. out-proj: N=256, 64x64 -> grid 4x96
    launch_pdl(kOP, dim3(4, 96), dim3(256), (size_t)SMSML,
               (const __nv_bfloat16*)attnb, (const __nv_bfloat16*)wo, out_b, (void*)tmp);
    // 5. x1 = LN(x + proj), dual write fp32 + bf16
    launch_pdl(ln_kernel<true>, dim3(N_TOK / 8), dim3(256), (size_t)0,
               (const float*)tmp, x, ln1_g, ln1_b, x1, x1b);
    // 6. FF1: N=1024, 128x128 -> grid 8x48, gelu, bf16 out
    launch_pdl(kFF1, dim3(8, 48), dim3(256), (size_t)SMBIG,
               (const __nv_bfloat16*)x1b, (const __nv_bfloat16*)w1, ff_b1, (void*)ffhb);
    // 7. FF2: N=256, 64x64 -> grid 4x96
    launch_pdl(kFF2, dim3(4, 96), dim3(256), (size_t)SMSML,
               (const __nv_bfloat16*)ffhb, (const __nv_bfloat16*)w2, ff_b2, (void*)tmp);
    // 8. out = LN(x1 + ff)
    launch_pdl(ln_kernel<false>, dim3(N_TOK / 8), dim3(256), (size_t)0,
               (const float*)tmp, (const float*)x1, ln2_g, ln2_b, out, (__nv_bfloat16*)nullptr);
}

// round 15
// speedup vs baseline: 1.1463x; 1.0023x over previous
#include <cuda_runtime.h>
#include <cuda_bf16.h>
#include <math.h>

#define N_TOK 6144
#define D_MODEL 256
#define N_HEADS 4
#define D_HEAD 64
#define D_FF 1024
#define LN_EPS 1e-5f

// ---------------- scratch (static device globals; no allocation) ----------------
__device__ float g_x1  [N_TOK * D_MODEL];
__device__ float g_tmp [N_TOK * D_MODEL];
__device__ __nv_bfloat16 g_qkvb [N_TOK * 3 * D_MODEL];  // bf16 qkv (attention reads)
__device__ __nv_bfloat16 g_xb   [N_TOK * D_MODEL];      // bf16 activations/weights
__device__ __nv_bfloat16 g_attnb[N_TOK * D_MODEL];
__device__ __nv_bfloat16 g_x1b  [N_TOK * D_MODEL];
__device__ __nv_bfloat16 g_ffhb [N_TOK * D_FF];
__device__ __nv_bfloat16 g_wq   [D_MODEL * 3 * D_MODEL];
__device__ __nv_bfloat16 g_wo   [D_MODEL * D_MODEL];
__device__ __nv_bfloat16 g_w1   [D_MODEL * D_FF];
__device__ __nv_bfloat16 g_w2   [D_FF * D_MODEL];

// ---------------- helpers --------------------------------------------------------
__device__ __forceinline__ void cp16(void* smem_dst, const void* gsrc) {
    unsigned d = (unsigned)__cvta_generic_to_shared(smem_dst);
    asm volatile("cp.async.cg.shared.global [%0], [%1], 16;\n" :: "r"(d), "l"(gsrc));
}
__device__ __forceinline__ void cp_commit() { asm volatile("cp.async.commit_group;\n"); }
template<int NLEFT>
__device__ __forceinline__ void cp_wait()   { asm volatile("cp.async.wait_group %0;\n" :: "n"(NLEFT)); }

__device__ __forceinline__ void ldsm_x4(unsigned& r0, unsigned& r1, unsigned& r2, unsigned& r3,
                                        const void* p) {
    unsigned a = (unsigned)__cvta_generic_to_shared(p);
    asm volatile("ldmatrix.sync.aligned.m8n8.x4.shared.b16 {%0,%1,%2,%3}, [%4];"
                 : "=r"(r0), "=r"(r1), "=r"(r2), "=r"(r3) : "r"(a));
}
__device__ __forceinline__ void ldsm_x2t(unsigned& r0, unsigned& r1, const void* p) {
    unsigned a = (unsigned)__cvta_generic_to_shared(p);
    asm volatile("ldmatrix.sync.aligned.m8n8.x2.trans.shared.b16 {%0,%1}, [%2];"
                 : "=r"(r0), "=r"(r1) : "r"(a));
}
__device__ __forceinline__ void mma_bf16(
    float& c0, float& c1, float& c2, float& c3,
    unsigned a0, unsigned a1, unsigned a2, unsigned a3,
    unsigned b0, unsigned b1)
{
    asm volatile(
        "mma.sync.aligned.m16n8k16.row.col.f32.bf16.bf16.f32 "
        "{%0,%1,%2,%3}, {%4,%5,%6,%7}, {%8,%9}, {%0,%1,%2,%3};\n"
        : "+f"(c0), "+f"(c1), "+f"(c2), "+f"(c3)
        : "r"(a0), "r"(a1), "r"(a2), "r"(a3), "r"(b0), "r"(b1));
}

// Canonical PDL pattern: sync-then-trigger at kernel start.
__device__ __forceinline__ void pdl_entry() {
    cudaGridDependencySynchronize();
    cudaTriggerProgrammaticLaunchCompletion();
}

// ---------------- bf16 tensor-core GEMM, BK=64, 3-stage cp.async pipeline --------
#define BK 64
#define NSTG 3
#define A_STR 72    // 64 + 8 pad, words; stride 144B -> conflict-free ldmatrix

template<int BM, int BN> struct GemmCfg {
    static constexpr int B_STR = (BN == 128) ? 136 : 72;
    static constexpr int SMEM  = (NSTG * BM * A_STR + NSTG * BK * B_STR) * 2;
};

template<int K, int N, int BM, int BN, bool DOGELU, bool OUTBF16>
__global__ __launch_bounds__(256, (BM == 128) ? 2 : 3) void gemm_bf16_k(
    const __nv_bfloat16* __restrict__ A, const __nv_bfloat16* __restrict__ B,
    const float* __restrict__ bias, void* __restrict__ Cv)
{
    pdl_entry();

    constexpr int B_STR = GemmCfg<BM, BN>::B_STR;
    constexpr int WM = BM / 2;
    constexpr int WN = BN / 4;
    constexpr int MI = WM / 16;
    constexpr int NI = WN / 8;
    constexpr int KS = BK / 16;
    constexpr bool DB = (MI * NI <= 4);

    extern __shared__ __nv_bfloat16 smdyn[];
    typedef __nv_bfloat16 (*AsT)[BM][A_STR];
    typedef __nv_bfloat16 (*BsT)[BK][B_STR];
    AsT As = reinterpret_cast<AsT>(smdyn);
    BsT Bs = reinterpret_cast<BsT>(smdyn + NSTG * BM * A_STR);

    const int tid  = threadIdx.x;
    const int row0 = blockIdx.y * BM;
    const int col0 = blockIdx.x * BN;
    const int w    = tid >> 5;
    const int lane = tid & 31;
    const int wm = w & 1;
    const int wn = w >> 1;
    const int g  = lane >> 2;
    const int t4 = lane & 3;

    float acc[MI][NI][4];
#pragma unroll
    for (int mi = 0; mi < MI; mi++)
#pragma unroll
        for (int ni = 0; ni < NI; ni++)
#pragma unroll
            for (int r = 0; r < 4; r++) acc[mi][ni][r] = 0.f;

    auto stage = [&](int kt, int buf) {
#pragma unroll
        for (int c = tid; c < BM * 8; c += 256) {
            int r = c >> 3, col = (c & 7) * 8;
            cp16(&As[buf][r][col], A + (size_t)(row0 + r) * K + kt + col);
        }
#pragma unroll
        for (int c = tid; c < 8 * BN; c += 256) {
            int r = c / (BN / 8), col = (c % (BN / 8)) * 8;
            cp16(&Bs[buf][r][col], B + (size_t)(kt + r) * N + col0 + col);
        }
        cp_commit();
    };

    constexpr int T = K / BK;
    static_assert(T >= 2, "need at least 2 k-slabs");
    stage(0, 0);
    stage(BK, 1);

    const int a_row = lane & 15;
    const int a_col = ((lane >> 4) << 3);
    const int b_row = lane & 15;

    auto load_frags = [&](unsigned (&af)[MI][4], unsigned (&bf)[NI][2], int buf, int ks) {
        const int kc = ks * 16;
#pragma unroll
        for (int mi = 0; mi < MI; mi++)
            ldsm_x4(af[mi][0], af[mi][1], af[mi][2], af[mi][3],
                    &As[buf][wm * WM + mi * 16 + a_row][kc + a_col]);
#pragma unroll
        for (int ni = 0; ni < NI; ni++)
            ldsm_x2t(bf[ni][0], bf[ni][1], &Bs[buf][kc + b_row][wn * WN + ni * 8]);
    };
    auto mma_all = [&](unsigned (&af)[MI][4], unsigned (&bf)[NI][2]) {
#pragma unroll
        for (int mi = 0; mi < MI; mi++)
#pragma unroll
            for (int ni = 0; ni < NI; ni++)
                mma_bf16(acc[mi][ni][0], acc[mi][ni][1], acc[mi][ni][2], acc[mi][ni][3],
                         af[mi][0], af[mi][1], af[mi][2], af[mi][3],
                         bf[ni][0], bf[ni][1]);
    };

    for (int t = 0; t < T; t++) {
        cp_wait<1>();
        __syncthreads();
        if (t + 2 < T) stage((t + 2) * BK, (t + 2) % 3);
        else cp_commit();
        const int buf = t % 3;

        if (DB) {
            unsigned af[2][MI][4], bf[2][NI][2];
            load_frags(af[0], bf[0], buf, 0);
#pragma unroll
            for (int ks = 0; ks < KS; ks++) {
                const int cur = ks & 1;
                if (ks + 1 < KS) load_frags(af[cur ^ 1], bf[cur ^ 1], buf, ks + 1);
                mma_all(af[cur], bf[cur]);
            }
        } else {
#pragma unroll
            for (int ks = 0; ks < KS; ks++) {
                unsigned af[MI][4], bf[NI][2];
                load_frags(af, bf, buf, ks);
                mma_all(af, bf);
            }
        }
    }

    // epilogue: bias (+gelu)
#pragma unroll
    for (int mi = 0; mi < MI; mi++) {
        const int r0g = row0 + wm * WM + mi * 16 + g;
#pragma unroll
        for (int ni = 0; ni < NI; ni++) {
            const int c = col0 + wn * WN + ni * 8 + t4 * 2;
            const float bx = bias[c], by = bias[c + 1];
            float v0 = acc[mi][ni][0] + bx, v1 = acc[mi][ni][1] + by;
            float v2 = acc[mi][ni][2] + bx, v3 = acc[mi][ni][3] + by;
            if (DOGELU) {
                v0 = 0.5f * v0 * (1.f + erff(v0 * 0.70710678118654752f));
                v1 = 0.5f * v1 * (1.f + erff(v1 * 0.70710678118654752f));
                v2 = 0.5f * v2 * (1.f + erff(v2 * 0.70710678118654752f));
                v3 = 0.5f * v3 * (1.f + erff(v3 * 0.70710678118654752f));
            }
            if (OUTBF16) {
                __nv_bfloat16* C = (__nv_bfloat16*)Cv;
                *reinterpret_cast<__nv_bfloat162*>(C + (size_t)r0g * N + c) =
                    __floats2bfloat162_rn(v0, v1);
                *reinterpret_cast<__nv_bfloat162*>(C + (size_t)(r0g + 8) * N + c) =
                    __floats2bfloat162_rn(v2, v3);
            } else {
                float* C = (float*)Cv;
                *reinterpret_cast<float2*>(C + (size_t)r0g * N + c)       = make_float2(v0, v1);
                *reinterpret_cast<float2*>(C + (size_t)(r0g + 8) * N + c) = make_float2(v2, v3);
            }
        }
    }
}

// ---------------- fp32 -> bf16 conversion of x + weights (one kernel) ------------
#define Q_X   393216           // 6144*256/4
#define Q_WQ  (Q_X  + 49152)   // 256*768/4
#define Q_WO  (Q_WQ + 16384)   // 256*256/4
#define Q_W1  (Q_WO + 65536)   // 256*1024/4
#define Q_W2  (Q_W1 + 65536)   // 1024*256/4  -> total 589824 quads
__global__ __launch_bounds__(256) void cvt_kernel(
    const float* __restrict__ x,  const float* __restrict__ wq,
    const float* __restrict__ wo, const float* __restrict__ w1,
    const float* __restrict__ w2,
    __nv_bfloat16* __restrict__ xb, __nv_bfloat16* __restrict__ wqb,
    __nv_bfloat16* __restrict__ wob, __nv_bfloat16* __restrict__ w1b,
    __nv_bfloat16* __restrict__ w2b)
{
    int q = blockIdx.x * 256 + threadIdx.x;
    const float* s; __nv_bfloat16* d; int base;
    if      (q < Q_X)  { s = x;  d = xb;  base = 0;    }
    else if (q < Q_WQ) { s = wq; d = wqb; base = Q_X;  }
    else if (q < Q_WO) { s = wo; d = wob; base = Q_WQ; }
    else if (q < Q_W1) { s = w1; d = w1b; base = Q_WO; }
    else               { s = w2; d = w2b; base = Q_W1; }
    size_t i = (size_t)(q - base) * 4;
    float4 v = *reinterpret_cast<const float4*>(s + i);
    reinterpret_cast<__nv_bfloat162*>(d + i)[0] = __floats2bfloat162_rn(v.x, v.y);
    reinterpret_cast<__nv_bfloat162*>(d + i)[1] = __floats2bfloat162_rn(v.z, v.w);
}

// ---------------- segment attention: one warp per TOKEN, 4 heads in-lane --------
// qkv is bf16: each lane's 8 dims = one ld.128 per K row and per V row.
// Math in fp32. Segment bounds via ballot over a 32-token window (doc sorted).
__global__ __launch_bounds__(256) void attn_kernel(
    const __nv_bfloat16* __restrict__ qkv, const int* __restrict__ doc,
    __nv_bfloat16* __restrict__ out)
{
    const int i    = blockIdx.x * 8 + (threadIdx.x >> 5);   // token
    const int lane = threadIdx.x & 31;
    const int h    = lane >> 3;
    const int sub  = lane & 7;
    const int doff = h * D_HEAD + sub * 8;                  // this lane's 8 dims

    const int my = doc[i];
    const int base = i - 16;
    const int idx = base + lane;
    int dv = -1;
    if (idx >= 0 && idx < N_TOK) dv = doc[idx];
    unsigned eq = __ballot_sync(0xffffffffu, dv == my);

    unsigned below = ~eq & 0xffffu;
    int s = (below == 0) ? base : base + (32 - __clz(below));
    unsigned above = ~eq & 0xfffe0000u;
    int e = (above == 0) ? base + 32 : base + (__ffs(above) - 1);
    if (below == 0) { while (s > 0 && doc[s - 1] == my) s--; }
    if (above == 0) { while (e < N_TOK && doc[e] == my) e++; }

    pdl_entry();     // qkv (producer data) read only below this point

    // q: 8 bf16 = one 16B load, convert to fp32
    float qf[8];
    {
        uint4 qr = *reinterpret_cast<const uint4*>(qkv + (size_t)i * (3 * D_MODEL) + doff);
        const __nv_bfloat162* qp = reinterpret_cast<const __nv_bfloat162*>(&qr);
#pragma unroll
        for (int t = 0; t < 4; t++) {
            float2 f = __bfloat1622float2(qp[t]);
            qf[2 * t] = f.x; qf[2 * t + 1] = f.y;
        }
    }

    const __nv_bfloat16* kbase = qkv + D_MODEL + doff;
    const __nv_bfloat16* vbase = qkv + 2 * D_MODEL + doff;

    float m = -3.4e38f, sum = 0.f;
    float o[8];
#pragma unroll
    for (int t = 0; t < 8; t++) o[t] = 0.f;

    for (int j = s; j < e; j++) {
        const size_t roff = (size_t)j * (3 * D_MODEL);
        uint4 kr = *reinterpret_cast<const uint4*>(kbase + roff);
        const __nv_bfloat162* kp = reinterpret_cast<const __nv_bfloat162*>(&kr);
        float d = 0.f;
#pragma unroll
        for (int t = 0; t < 4; t++) {
            float2 f = __bfloat1622float2(kp[t]);
            d += qf[2 * t] * f.x + qf[2 * t + 1] * f.y;
        }
        // reduce within 8-lane group: 4 heads reduced simultaneously
        d += __shfl_xor_sync(0xffffffffu, d, 1);
        d += __shfl_xor_sync(0xffffffffu, d, 2);
        d += __shfl_xor_sync(0xffffffffu, d, 4);
        float sc = d * 0.125f;                  // 1/sqrt(64)
        float mn = fmaxf(m, sc);
        float corr = __expf(m - mn);
        float p = __expf(sc - mn);
        uint4 vr = *reinterpret_cast<const uint4*>(vbase + roff);
        const __nv_bfloat162* vp = reinterpret_cast<const __nv_bfloat162*>(&vr);
#pragma unroll
        for (int t = 0; t < 4; t++) {
            float2 f = __bfloat1622float2(vp[t]);
            o[2 * t]     = o[2 * t]     * corr + p * f.x;
            o[2 * t + 1] = o[2 * t + 1] * corr + p * f.y;
        }
        sum = sum * corr + p;
        m = mn;
    }
    float inv = 1.f / sum;
    __nv_bfloat162 r[4];
#pragma unroll
    for (int t = 0; t < 4; t++)
        r[t] = __floats2bfloat162_rn(o[2 * t] * inv, o[2 * t + 1] * inv);
    *reinterpret_cast<uint4*>(out + (size_t)i * D_MODEL + doff) =
        *reinterpret_cast<const uint4*>(r);
}

// ---------------- residual + layernorm: warp per row; optional bf16 dual write --
template<bool DUAL>
__global__ __launch_bounds__(256) void ln_kernel(
    const float* __restrict__ y, const float* __restrict__ res,
    const float* __restrict__ gw, const float* __restrict__ bw,
    float* __restrict__ out, __nv_bfloat16* __restrict__ outb)
{
    pdl_entry();
    int row = blockIdx.x * 8 + (threadIdx.x >> 5);
    int lane = threadIdx.x & 31;
    size_t base = (size_t)row * D_MODEL;

    float4 a0 = *reinterpret_cast<const float4*>(y + base + lane * 4);
    float4 r0 = *reinterpret_cast<const float4*>(res + base + lane * 4);
    float4 a1 = *reinterpret_cast<const float4*>(y + base + 128 + lane * 4);
    float4 r1 = *reinterpret_cast<const float4*>(res + base + 128 + lane * 4);
    a0.x += r0.x; a0.y += r0.y; a0.z += r0.z; a0.w += r0.w;
    a1.x += r1.x; a1.y += r1.y; a1.z += r1.z; a1.w += r1.w;

    float s  = a0.x + a0.y + a0.z + a0.w + a1.x + a1.y + a1.z + a1.w;
    float sq = a0.x*a0.x + a0.y*a0.y + a0.z*a0.z + a0.w*a0.w
             + a1.x*a1.x + a1.y*a1.y + a1.z*a1.z + a1.w*a1.w;
#pragma unroll
    for (int o = 16; o; o >>= 1) {
        s  += __shfl_xor_sync(0xffffffffu, s, o);
        sq += __shfl_xor_sync(0xffffffffu, sq, o);
    }
    float mu  = s * (1.f / D_MODEL);
    float var = sq * (1.f / D_MODEL) - mu * mu;
    float inv = rsqrtf(var + LN_EPS);

    float4 g0 = *reinterpret_cast<const float4*>(gw + lane * 4);
    float4 b0 = *reinterpret_cast<const float4*>(bw + lane * 4);
    float4 g1 = *reinterpret_cast<const float4*>(gw + 128 + lane * 4);
    float4 b1 = *reinterpret_cast<const float4*>(bw + 128 + lane * 4);
    float4 o0, o1;
    o0.x = (a0.x - mu) * inv * g0.x + b0.x;
    o0.y = (a0.y - mu) * inv * g0.y + b0.y;
    o0.z = (a0.z - mu) * inv * g0.z + b0.z;
    o0.w = (a0.w - mu) * inv * g0.w + b0.w;
    o1.x = (a1.x - mu) * inv * g1.x + b1.x;
    o1.y = (a1.y - mu) * inv * g1.y + b1.y;
    o1.z = (a1.z - mu) * inv * g1.z + b1.z;
    o1.w = (a1.w - mu) * inv * g1.w + b1.w;
    *reinterpret_cast<float4*>(out + base + lane * 4)       = o0;
    *reinterpret_cast<float4*>(out + base + 128 + lane * 4) = o1;
    if (DUAL) {
        reinterpret_cast<__nv_bfloat162*>(outb + base + lane * 4)[0] = __floats2bfloat162_rn(o0.x, o0.y);
        reinterpret_cast<__nv_bfloat162*>(outb + base + lane * 4)[1] = __floats2bfloat162_rn(o0.z, o0.w);
        reinterpret_cast<__nv_bfloat162*>(outb + base + 128 + lane * 4)[0] = __floats2bfloat162_rn(o1.x, o1.y);
        reinterpret_cast<__nv_bfloat162*>(outb + base + 128 + lane * 4)[1] = __floats2bfloat162_rn(o1.z, o1.w);
    }
}

// ---------------- PDL launch helper ----------------------------------------------
template<typename F, typename... Args>
static inline void launch_pdl(F* f, dim3 grid, dim3 block, size_t smem, Args... args) {
    cudaLaunchConfig_t cfg = {};
    cfg.gridDim = grid;
    cfg.blockDim = block;
    cfg.dynamicSmemBytes = smem;
    cfg.stream = 0;
    cudaLaunchAttribute at[1];
    at[0].id = cudaLaunchAttributeProgrammaticStreamSerialization;
    at[0].val.programmaticStreamSerializationAllowed = 1;
    cfg.attrs = at;
    cfg.numAttrs = 1;
    cudaLaunchKernelEx(&cfg, f, args...);
}

// ---------------- launch ---------------------------------------------------------
extern "C" void kernel_launch(void* const* d_in, const int* in_sizes, int n_in,
                              void* d_out, int out_size)
{
    const float* x      = (const float*)d_in[0];
    const int*   doc    = (const int*)  d_in[1];
    const float* qkv_w  = (const float*)d_in[2];
    const float* qkv_b  = (const float*)d_in[3];
    const float* out_w  = (const float*)d_in[4];
    const float* out_b  = (const float*)d_in[5];
    const float* ff_w1  = (const float*)d_in[6];
    const float* ff_b1  = (const float*)d_in[7];
    const float* ff_w2  = (const float*)d_in[8];
    const float* ff_b2  = (const float*)d_in[9];
    const float* ln1_g  = (const float*)d_in[10];
    const float* ln1_b  = (const float*)d_in[11];
    const float* ln2_g  = (const float*)d_in[12];
    const float* ln2_b  = (const float*)d_in[13];
    float* out = (float*)d_out;

    float *x1, *tmp;
    __nv_bfloat16 *qkvb, *xb, *attnb, *x1b, *ffhb, *wq, *wo, *w1, *w2;
    cudaGetSymbolAddress((void**)&qkvb,  g_qkvb);
    cudaGetSymbolAddress((void**)&x1,    g_x1);
    cudaGetSymbolAddress((void**)&tmp,   g_tmp);
    cudaGetSymbolAddress((void**)&xb,    g_xb);
    cudaGetSymbolAddress((void**)&attnb, g_attnb);
    cudaGetSymbolAddress((void**)&x1b,   g_x1b);
    cudaGetSymbolAddress((void**)&ffhb,  g_ffhb);
    cudaGetSymbolAddress((void**)&wq,    g_wq);
    cudaGetSymbolAddress((void**)&wo,    g_wo);
    cudaGetSymbolAddress((void**)&w1,    g_w1);
    cudaGetSymbolAddress((void**)&w2,    g_w2);

    // opt-in to >48KB dynamic smem (idempotent host-side attribute sets)
    constexpr int SMBIG = GemmCfg<128, 128>::SMEM;   // 107520
    constexpr int SMSML = GemmCfg<64, 64>::SMEM;     // 55296
    auto* kQKV = gemm_bf16_k<D_MODEL, 3 * D_MODEL, 128, 128, false, true>;
    auto* kOP  = gemm_bf16_k<D_MODEL, D_MODEL, 64, 64, false, false>;
    auto* kFF1 = gemm_bf16_k<D_MODEL, D_FF, 128, 128, true, true>;
    auto* kFF2 = gemm_bf16_k<D_FF, D_MODEL, 64, 64, false, false>;
    cudaFuncSetAttribute((const void*)kQKV, cudaFuncAttributeMaxDynamicSharedMemorySize, SMBIG);
    cudaFuncSetAttribute((const void*)kFF1, cudaFuncAttributeMaxDynamicSharedMemorySize, SMBIG);
    cudaFuncSetAttribute((const void*)kOP,  cudaFuncAttributeMaxDynamicSharedMemorySize, SMSML);
    cudaFuncSetAttribute((const void*)kFF2, cudaFuncAttributeMaxDynamicSharedMemorySize, SMSML);

    // 1. fp32->bf16 conversions (first kernel; plain launch)
    cvt_kernel<<<Q_W2 / 256, 256>>>(x, qkv_w, out_w, ff_w1, ff_w2, xb, wq, wo, w1, w2);
    // 2. QKV: N=768, 128x128 -> grid 6x48, bf16 out
    launch_pdl(kQKV, dim3(6, 48), dim3(256), (size_t)SMBIG,
               (const __nv_bfloat16*)xb, (const __nv_bfloat16*)wq, qkv_b, (void*)qkvb);
    // 3. segment attention: warp per token -> 768 CTAs (reads bf16 qkv)
    launch_pdl(attn_kernel, dim3(N_TOK / 8), dim3(256), (size_t)0,
               (const __nv_bfloat16*)qkvb, doc, attnb);
    // 4. out-proj: N=256, 64x64 -> grid 4x96
    launch_pdl(kOP, dim3(4, 96), dim3(256), (size_t)SMSML,
               (const __nv_bfloat16*)attnb, (const __nv_bfloat16*)wo, out_b, (void*)tmp);
    // 5. x1 = LN(x + proj), dual write fp32 + bf16
    launch_pdl(ln_kernel<true>, dim3(N_TOK / 8), dim3(256), (size_t)0,
               (const float*)tmp, x, ln1_g, ln1_b, x1, x1b);
    // 6. FF1: N=1024, 128x128 -> grid 8x48, gelu, bf16 out
    launch_pdl(kFF1, dim3(8, 48), dim3(256), (size_t)SMBIG,
               (const __nv_bfloat16*)x1b, (const __nv_bfloat16*)w1, ff_b1, (void*)ffhb);
    // 7. FF2: N=256, 64x64 -> grid 4x96
    launch_pdl(kFF2, dim3(4, 96), dim3(256), (size_t)SMSML,
               (const __nv_bfloat16*)ffhb, (const __nv_bfloat16*)w2, ff_b2, (void*)tmp);
    // 8. out = LN(x1 + ff)
    launch_pdl(ln_kernel<false>, dim3(N_TOK / 8), dim3(256), (size_t)0,
               (const float*)tmp, (const float*)x1, ln2_g, ln2_b, out, (__nv_bfloat16*)nullptr);
}